// round 10
// baseline (speedup 1.0000x reference)
#include <cuda_runtime.h>
#include <cuda_bf16.h>
#include <cstdint>
#include <math.h>

#define BB 4
#define TT 2048
#define CC 1024
#define HH 16
#define HD 64
#define BH (BB*HH)   /* 64 */
#define MM (BB*TT)   /* 8192 */

// ------------------------- scratch (static device globals; no allocs) ---------
__device__ __nv_bfloat16 g_xb[(size_t)MM*CC];          // x in bf16
__device__ __nv_bfloat16 g_WT[4][(size_t)CC*CC];       // Wq,Wk,Wv,Wo transposed [n][k] bf16
__device__ __nv_bfloat16 g_bias[4][CC];                // bq,bk,bv,bo bf16
__device__ __nv_bfloat16 g_q[(size_t)BH*TT*HD];        // [bh][t][d] post-rope bf16
__device__ __nv_bfloat16 g_k[(size_t)BH*TT*HD];
__device__ __nv_bfloat16 g_v[(size_t)BH*TT*HD];
__device__ __nv_bfloat16 g_S[(size_t)BH*TT*TT];        // bf16 scaled logits (lower-tri tiles)
__device__ float         g_E[(size_t)BH*TT*TT];        // f32 exp(s-m) (lower-tri, causal only)
__device__ __nv_bfloat16 g_y[(size_t)MM*CC];           // attention output bf16 [b*T+t][h*64+d]
__device__ float         g_cos[TT*(HD/2)];
__device__ float         g_sin[TT*(HD/2)];

// ------------------------- accurate f32 exp (cephes/Eigen pexp style) ---------
__device__ __forceinline__ float exp_rn(float x) {
    x = fmaxf(x, -87.0f);
    float mf = floorf(__fmaf_rn(x, 1.44269504088896341f, 0.5f));
    float r  = __fmaf_rn(mf, -0.693359375f, x);
    r        = __fmaf_rn(mf,  2.12194440e-4f, r);
    float p  = 1.9875691500e-4f;
    p = __fmaf_rn(p, r, 1.3981999507e-3f);
    p = __fmaf_rn(p, r, 8.3334519073e-3f);
    p = __fmaf_rn(p, r, 4.1665795894e-2f);
    p = __fmaf_rn(p, r, 1.6666665459e-1f);
    p = __fmaf_rn(p, r, 5.0000001201e-1f);
    float y = __fmaf_rn(p, __fmul_rn(r, r), r);
    y = __fadd_rn(y, 1.0f);
    int mi = (int)mf;
    float sc = __int_as_float((mi + 127) << 23);
    return __fmul_rn(y, sc);
}

// ------------------------- mma.sync m16n8k16 bf16 -----------------------------
__device__ __forceinline__ void mma_bf16(float c[4], const uint32_t a[4], const uint32_t b[2]) {
    asm volatile(
        "mma.sync.aligned.m16n8k16.row.col.f32.bf16.bf16.f32 "
        "{%0,%1,%2,%3}, {%4,%5,%6,%7}, {%8,%9}, {%0,%1,%2,%3};\n"
        : "+f"(c[0]), "+f"(c[1]), "+f"(c[2]), "+f"(c[3])
        : "r"(a[0]), "r"(a[1]), "r"(a[2]), "r"(a[3]), "r"(b[0]), "r"(b[1]));
}

// ------------------------- prep kernels ---------------------------------------
__global__ void k_conv_x(const float* __restrict__ x) {
    size_t i = ((size_t)blockIdx.x * 256 + threadIdx.x) * 4;
    float4 v = *(const float4*)(x + i);
    __nv_bfloat162 a, b;
    a.x = __float2bfloat16(v.x); a.y = __float2bfloat16(v.y);
    b.x = __float2bfloat16(v.z); b.y = __float2bfloat16(v.w);
    *(__nv_bfloat162*)(g_xb + i)     = a;
    *(__nv_bfloat162*)(g_xb + i + 2) = b;
}

__global__ void k_prepW(const float* __restrict__ Wq, const float* __restrict__ Wk,
                        const float* __restrict__ Wv, const float* __restrict__ Wo) {
    const float* W = (blockIdx.z == 0) ? Wq : (blockIdx.z == 1) ? Wk : (blockIdx.z == 2) ? Wv : Wo;
    __shared__ float tile[32][33];
    int n0 = blockIdx.x * 32, k0 = blockIdx.y * 32;
    for (int jj = threadIdx.y; jj < 32; jj += 8)
        tile[jj][threadIdx.x] = W[(size_t)(k0 + jj) * CC + n0 + threadIdx.x];
    __syncthreads();
    for (int jj = threadIdx.y; jj < 32; jj += 8)
        g_WT[blockIdx.z][(size_t)(n0 + jj) * CC + k0 + threadIdx.x] =
            __float2bfloat16(tile[threadIdx.x][jj]);
}

__global__ void k_biasprep(const float* __restrict__ bq, const float* __restrict__ bk,
                           const float* __restrict__ bv, const float* __restrict__ bo) {
    const float* p = (blockIdx.x == 0) ? bq : (blockIdx.x == 1) ? bk : (blockIdx.x == 2) ? bv : bo;
    g_bias[blockIdx.x][threadIdx.x] = __float2bfloat16(p[threadIdx.x]);
}

__global__ void k_rope() {
    int t = blockIdx.x, j = threadIdx.x;                 // j in 0..31
    double e = (double)(2 * j) / 64.0;
    float p32 = (float)pow(10000.0, e);                  // f32 rounding of pow
    float inv = __fdiv_rn(1.0f, p32);                    // f32 reciprocal
    float ang = __fmul_rn((float)t, inv);                // f32 angle
    g_cos[t * (HD/2) + j] = (float)cos((double)ang);
    g_sin[t * (HD/2) + j] = (float)sin((double)ang);
}

// ------------------------- GEMM: x@W (+bias, rope) / y@Wo --------------------
// 128x128 tile, k-tile 64, cp.async 3-stage ring (wait_group 1), 256 threads.
#define GSTAGE 36864              /* bytes per stage: (A 128*72 + B 128*72) * 2B */
#define GSMEM  (3*GSTAGE)

__global__ __launch_bounds__(256) void k_gemm(int mode_base, float* __restrict__ outF)
{
    extern __shared__ unsigned char gsm[];
    const int mode = mode_base + blockIdx.z;             // 0=q 1=k 2=v 3=out-proj
    const __nv_bfloat16* __restrict__ A  = (mode < 3) ? g_xb : g_y;
    const __nv_bfloat16* __restrict__ Bt = g_WT[mode];
    const __nv_bfloat16* __restrict__ bs = g_bias[mode];
    const int m0 = blockIdx.y * 128;
    const int n0 = blockIdx.x * 128;

    const int tid = threadIdx.x;
    const int wid = tid >> 5, lane = tid & 31;
    const int g = lane >> 2, t4 = lane & 3;
    const int wm = wid & 3, wn = wid >> 2;

    float acc[16][4];
    #pragma unroll
    for (int i = 0; i < 16; i++) { acc[i][0] = acc[i][1] = acc[i][2] = acc[i][3] = 0.f; }

    // prologue: prefetch stages 0 and 1
    #pragma unroll
    for (int pre = 0; pre < 2; pre++) {
        int k0 = pre * 64;
        __nv_bfloat16* sA = (__nv_bfloat16*)(gsm + pre * GSTAGE);
        __nv_bfloat16* sB = (__nv_bfloat16*)(gsm + pre * GSTAGE + GSTAGE / 2);
        #pragma unroll
        for (int rep = 0; rep < 4; rep++) {
            int i = tid + rep * 256;
            int row = i >> 3, cg = i & 7;
            uint32_t da = (uint32_t)__cvta_generic_to_shared(sA + row * 72 + cg * 8);
            uint32_t db = (uint32_t)__cvta_generic_to_shared(sB + row * 72 + cg * 8);
            asm volatile("cp.async.cg.shared.global [%0], [%1], 16;\n"
                         :: "r"(da), "l"(A  + (size_t)(m0 + row) * CC + k0 + cg * 8));
            asm volatile("cp.async.cg.shared.global [%0], [%1], 16;\n"
                         :: "r"(db), "l"(Bt + (size_t)(n0 + row) * CC + k0 + cg * 8));
        }
        asm volatile("cp.async.commit_group;\n");
    }

    for (int it = 0; it < 16; it++) {
        asm volatile("cp.async.wait_group 1;\n");
        __syncthreads();
        if (it + 2 < 16) {
            int k0 = (it + 2) * 64;
            unsigned char* stg = gsm + ((it + 2) % 3) * GSTAGE;
            __nv_bfloat16* sA = (__nv_bfloat16*)stg;
            __nv_bfloat16* sB = (__nv_bfloat16*)(stg + GSTAGE / 2);
            #pragma unroll
            for (int rep = 0; rep < 4; rep++) {
                int i = tid + rep * 256;
                int row = i >> 3, cg = i & 7;
                uint32_t da = (uint32_t)__cvta_generic_to_shared(sA + row * 72 + cg * 8);
                uint32_t db = (uint32_t)__cvta_generic_to_shared(sB + row * 72 + cg * 8);
                asm volatile("cp.async.cg.shared.global [%0], [%1], 16;\n"
                             :: "r"(da), "l"(A  + (size_t)(m0 + row) * CC + k0 + cg * 8));
                asm volatile("cp.async.cg.shared.global [%0], [%1], 16;\n"
                             :: "r"(db), "l"(Bt + (size_t)(n0 + row) * CC + k0 + cg * 8));
            }
            asm volatile("cp.async.commit_group;\n");
        } else {
            asm volatile("cp.async.commit_group;\n");    // keep group count in step
        }
        const __nv_bfloat16* sA = (const __nv_bfloat16*)(gsm + (it % 3) * GSTAGE);
        const __nv_bfloat16* sB = (const __nv_bfloat16*)(gsm + (it % 3) * GSTAGE + GSTAGE / 2);
        #pragma unroll
        for (int ks = 0; ks < 64; ks += 16) {
            uint32_t af[2][4];
            #pragma unroll
            for (int mt = 0; mt < 2; mt++) {
                int r = wm * 32 + mt * 16 + g;
                af[mt][0] = *(const uint32_t*)&sA[(r    ) * 72 + ks     + 2 * t4];
                af[mt][1] = *(const uint32_t*)&sA[(r + 8) * 72 + ks     + 2 * t4];
                af[mt][2] = *(const uint32_t*)&sA[(r    ) * 72 + ks + 8 + 2 * t4];
                af[mt][3] = *(const uint32_t*)&sA[(r + 8) * 72 + ks + 8 + 2 * t4];
            }
            uint32_t bfr[8][2];
            #pragma unroll
            for (int nt = 0; nt < 8; nt++) {
                int n = wn * 64 + nt * 8 + g;
                bfr[nt][0] = *(const uint32_t*)&sB[n * 72 + ks     + 2 * t4];
                bfr[nt][1] = *(const uint32_t*)&sB[n * 72 + ks + 8 + 2 * t4];
            }
            #pragma unroll
            for (int mt = 0; mt < 2; mt++)
                #pragma unroll
                for (int nt = 0; nt < 8; nt++)
                    mma_bf16(acc[mt * 8 + nt], af[mt], bfr[nt]);
        }
    }

    #pragma unroll
    for (int mt = 0; mt < 2; mt++) {
        #pragma unroll
        for (int nt = 0; nt < 8; nt++) {
            float* c = acc[mt * 8 + nt];
            int col = n0 + wn * 64 + nt * 8 + 2 * t4;
            int r0  = m0 + wm * 32 + mt * 16 + g;
            #pragma unroll
            for (int hf = 0; hf < 2; hf++) {
                int row = r0 + hf * 8;
                __nv_bfloat16 eb = __hadd(__float2bfloat16(c[hf * 2 + 0]), bs[col]);
                __nv_bfloat16 ob = __hadd(__float2bfloat16(c[hf * 2 + 1]), bs[col + 1]);
                if (mode == 3) {
                    outF[(size_t)row * CC + col]     = __bfloat162float(eb);
                    outF[(size_t)row * CC + col + 1] = __bfloat162float(ob);
                } else {
                    int b = row >> 11, t = row & (TT - 1);
                    int h = col >> 6,  d = col & 63;
                    size_t oidx = ((size_t)(b * HH + h) * TT + t) * HD + d;
                    __nv_bfloat162 pr;
                    if (mode <= 1) {                         // rope for q,k
                        int j = d >> 1;
                        float cth = g_cos[t * (HD/2) + j], sth = g_sin[t * (HD/2) + j];
                        float ef = __bfloat162float(eb), of = __bfloat162float(ob);
                        float re = __fsub_rn(__fmul_rn(ef, cth), __fmul_rn(of, sth));
                        float ro = __fadd_rn(__fmul_rn(ef, sth), __fmul_rn(of, cth));
                        pr.x = __float2bfloat16(re);
                        pr.y = __float2bfloat16(ro);
                    } else {
                        pr.x = eb; pr.y = ob;
                    }
                    __nv_bfloat16* outp = (mode == 0) ? g_q : (mode == 1) ? g_k : g_v;
                    *(__nv_bfloat162*)(outp + oidx) = pr;
                }
            }
        }
    }
}

// --------- fused attention: QK^T + max + l/exp-store (A) then p@V (B) ---------
__global__ __launch_bounds__(256) void k_att()
{
    __shared__ __align__(16) unsigned char buf[36864];
    __shared__ float sMax[2][64];
    __shared__ float sMfin[64];
    __shared__ float sLfin[64];

    const int qt = gridDim.x - 1 - blockIdx.x;           // heavy tiles first
    const int bh = blockIdx.y;
    const int q0 = qt * 64;
    const __nv_bfloat16* __restrict__ Q = g_q + (size_t)bh * TT * HD;
    const __nv_bfloat16* __restrict__ K = g_k + (size_t)bh * TT * HD;
    const __nv_bfloat16* __restrict__ V = g_v + (size_t)bh * TT * HD;

    const int tid = threadIdx.x;
    const int wid = tid >> 5, lane = tid & 31;
    const int g = lane >> 2, t4 = lane & 3;
    const int wm = wid & 3, wn = wid >> 2;
    const int r0 = wm * 16 + g;

    // ===================== phase A: S = bf16(QK^T)*0.125, max, l + e ==========
    {
        __nv_bfloat16* sQ = (__nv_bfloat16*)buf;                     // 9216 B
        #pragma unroll
        for (int rep = 0; rep < 2; rep++) {
            int i = tid + rep * 256;
            int row = i >> 3, cg = i & 7;
            *(uint4*)&sQ[row * 72 + cg * 8] = *(const uint4*)(Q + (size_t)(q0 + row) * HD + cg * 8);
        }
        // prestage K tile 0
        #pragma unroll
        for (int rep = 0; rep < 2; rep++) {
            int i = tid + rep * 256;
            int row = i >> 3, cg = i & 7;
            uint32_t dst = (uint32_t)__cvta_generic_to_shared(buf + 9216 + (row * 72 + cg * 8) * 2);
            asm volatile("cp.async.cg.shared.global [%0], [%1], 16;\n"
                         :: "r"(dst), "l"(K + (size_t)row * HD + cg * 8));
        }
        asm volatile("cp.async.commit_group;\n");

        const int qg0 = q0 + r0, qg1 = qg0 + 8;
        float rmax0 = -INFINITY, rmax1 = -INFINITY;

        for (int kt = 0; kt <= qt; kt++) {
            asm volatile("cp.async.wait_group 0;\n");
            __syncthreads();
            if (kt < qt) {
                unsigned char* dstb = buf + 9216 + ((kt + 1) & 1) * 9216;
                #pragma unroll
                for (int rep = 0; rep < 2; rep++) {
                    int i = tid + rep * 256;
                    int row = i >> 3, cg = i & 7;
                    uint32_t dst = (uint32_t)__cvta_generic_to_shared(dstb + (row * 72 + cg * 8) * 2);
                    asm volatile("cp.async.cg.shared.global [%0], [%1], 16;\n"
                                 :: "r"(dst), "l"(K + (size_t)((kt + 1) * 64 + row) * HD + cg * 8));
                }
                asm volatile("cp.async.commit_group;\n");
            }
            const __nv_bfloat16* sKb = (const __nv_bfloat16*)(buf + 9216 + (kt & 1) * 9216);
            float acc[4][4] = {};
            #pragma unroll
            for (int ks = 0; ks < 64; ks += 16) {
                uint32_t af[4];
                af[0] = *(const uint32_t*)&sQ[(r0    ) * 72 + ks     + 2 * t4];
                af[1] = *(const uint32_t*)&sQ[(r0 + 8) * 72 + ks     + 2 * t4];
                af[2] = *(const uint32_t*)&sQ[(r0    ) * 72 + ks + 8 + 2 * t4];
                af[3] = *(const uint32_t*)&sQ[(r0 + 8) * 72 + ks + 8 + 2 * t4];
                #pragma unroll
                for (int nt = 0; nt < 4; nt++) {
                    int n = wn * 32 + nt * 8 + g;
                    uint32_t bf2[2];
                    bf2[0] = *(const uint32_t*)&sKb[n * 72 + ks     + 2 * t4];
                    bf2[1] = *(const uint32_t*)&sKb[n * 72 + ks + 8 + 2 * t4];
                    mma_bf16(acc[nt], af, bf2);
                }
            }
            #pragma unroll
            for (int nt = 0; nt < 4; nt++) {
                int cl = wn * 32 + nt * 8 + 2 * t4;
                int kc = kt * 64 + cl;
                {
                    float s0 = __fmul_rn(__bfloat162float(__float2bfloat16(acc[nt][0])), 0.125f);
                    float s1 = __fmul_rn(__bfloat162float(__float2bfloat16(acc[nt][1])), 0.125f);
                    if (kc     <= qg0) rmax0 = fmaxf(rmax0, s0);
                    if (kc + 1 <= qg0) rmax0 = fmaxf(rmax0, s1);
                    __nv_bfloat162 pr; pr.x = __float2bfloat16(s0); pr.y = __float2bfloat16(s1);
                    *(__nv_bfloat162*)(g_S + (size_t)(bh * TT + qg0) * TT + kc) = pr;
                }
                {
                    float s0 = __fmul_rn(__bfloat162float(__float2bfloat16(acc[nt][2])), 0.125f);
                    float s1 = __fmul_rn(__bfloat162float(__float2bfloat16(acc[nt][3])), 0.125f);
                    if (kc     <= qg1) rmax1 = fmaxf(rmax1, s0);
                    if (kc + 1 <= qg1) rmax1 = fmaxf(rmax1, s1);
                    __nv_bfloat162 pr; pr.x = __float2bfloat16(s0); pr.y = __float2bfloat16(s1);
                    *(__nv_bfloat162*)(g_S + (size_t)(bh * TT + qg1) * TT + kc) = pr;
                }
            }
        }
        rmax0 = fmaxf(rmax0, __shfl_xor_sync(0xffffffffu, rmax0, 1));
        rmax0 = fmaxf(rmax0, __shfl_xor_sync(0xffffffffu, rmax0, 2));
        rmax1 = fmaxf(rmax1, __shfl_xor_sync(0xffffffffu, rmax1, 1));
        rmax1 = fmaxf(rmax1, __shfl_xor_sync(0xffffffffu, rmax1, 2));
        if (t4 == 0) {
            sMax[wn][wm * 16 + g]     = rmax0;
            sMax[wn][wm * 16 + g + 8] = rmax1;
        }
        __syncthreads();
        if (tid < 64) sMfin[tid] = fmaxf(sMax[0][tid], sMax[1][tid]);
        __syncthreads();   // S stripe writes + sMfin visible block-wide

        // l-pass over own stripe (L2-hot); e stored f32 for reuse in phase B.
        // Accumulation order identical to R8/R9; e values identical.
        {
            const int prow = tid >> 2;
            const int pcb  = (tid & 3) * 16;
            const int qgp  = q0 + prow;
            const float mrow = sMfin[prow];
            const __nv_bfloat16* __restrict__ Srow = g_S + (size_t)(bh * TT + qgp) * TT;
            float* __restrict__ Erow = g_E + (size_t)(bh * TT + qgp) * TT;
            float lp = 0.f;
            uint4 c0 = *(const uint4*)(Srow + pcb);
            uint4 c1 = *(const uint4*)(Srow + pcb + 8);
            for (int kt = 0; kt <= qt; kt++) {
                uint4 n0v, n1v;
                if (kt < qt) {
                    n0v = *(const uint4*)(Srow + (kt + 1) * 64 + pcb);
                    n1v = *(const uint4*)(Srow + (kt + 1) * 64 + pcb + 8);
                }
                __nv_bfloat16 hv[16];
                *(uint4*)&hv[0] = c0;
                *(uint4*)&hv[8] = c1;
                float ev[16];
                #pragma unroll
                for (int j = 0; j < 16; j++) {
                    int col = kt * 64 + pcb + j;
                    if (col <= qgp) {
                        ev[j] = exp_rn(__fsub_rn(__bfloat162float(hv[j]), mrow));
                        lp = __fadd_rn(lp, ev[j]);
                    } else {
                        ev[j] = 0.f;
                    }
                }
                #pragma unroll
                for (int v4 = 0; v4 < 4; v4++)
                    *(float4*)(Erow + kt * 64 + pcb + v4 * 4) = *(float4*)&ev[v4 * 4];
                c0 = n0v; c1 = n1v;
            }
            lp = __fadd_rn(lp, __shfl_xor_sync(0xffffffffu, lp, 1));
            lp = __fadd_rn(lp, __shfl_xor_sync(0xffffffffu, lp, 2));
            if ((tid & 3) == 0) sLfin[qgp - q0] = lp;
        }
    }
    __syncthreads();   // sLfin + g_E stripe ready; phase A smem dead from here

    // ===================== phase B: p = bf16(e/l), y = P@V^T ===================
    {
        const int prow = tid >> 2;
        const int pcb  = (tid & 3) * 16;
        const int qgp  = q0 + prow;
        const float lrow = sLfin[prow];
        const float* __restrict__ Erow = g_E + (size_t)(bh * TT + qgp) * TT;

        float acc[4][4] = {};

        // prolog: prefetch e chunk(kt=0) and V tile 0 into registers
        float4 e0 = *(const float4*)(Erow + pcb);
        float4 e1 = *(const float4*)(Erow + pcb + 4);
        float4 e2 = *(const float4*)(Erow + pcb + 8);
        float4 e3 = *(const float4*)(Erow + pcb + 12);
        uint4 vreg[2];
        #pragma unroll
        for (int rep = 0; rep < 2; rep++) {
            int i = tid + rep * 256;
            int vr = i >> 3, d0 = (i & 7) * 8;
            vreg[rep] = *(const uint4*)(V + (size_t)vr * HD + d0);
        }

        for (int kt = 0; kt <= qt; kt++) {
            const int bsel = kt & 1;
            __nv_bfloat16* sPb  = (__nv_bfloat16*)(buf + bsel * 9216);
            __nv_bfloat16* sVtb = (__nv_bfloat16*)(buf + 18432 + bsel * 9216);
            // probabilities: p = bf16(__fdiv_rn(e, l)) — e identical to R9's exp
            {
                float ev[16];
                *(float4*)&ev[0]  = e0;
                *(float4*)&ev[4]  = e1;
                *(float4*)&ev[8]  = e2;
                *(float4*)&ev[12] = e3;
                #pragma unroll
                for (int j = 0; j < 16; j += 2) {
                    int col = kt * 64 + pcb + j;
                    __nv_bfloat162 pr;
                    pr.x = (col     <= qgp) ? __float2bfloat16(__fdiv_rn(ev[j],     lrow))
                                            : __float2bfloat16(0.f);
                    pr.y = (col + 1 <= qgp) ? __float2bfloat16(__fdiv_rn(ev[j + 1], lrow))
                                            : __float2bfloat16(0.f);
                    *(__nv_bfloat162*)&sPb[prow * 72 + pcb + j] = pr;
                }
            }
            // store prefetched V tile transposed
            #pragma unroll
            for (int rep = 0; rep < 2; rep++) {
                int i = tid + rep * 256;
                int vr = i >> 3, d0 = (i & 7) * 8;
                __nv_bfloat16 tmp[8];
                *(uint4*)tmp = vreg[rep];
                #pragma unroll
                for (int j = 0; j < 8; j++) sVtb[(d0 + j) * 72 + vr] = tmp[j];
            }
            // prefetch next e chunk + V tile
            if (kt < qt) {
                e0 = *(const float4*)(Erow + (kt + 1) * 64 + pcb);
                e1 = *(const float4*)(Erow + (kt + 1) * 64 + pcb + 4);
                e2 = *(const float4*)(Erow + (kt + 1) * 64 + pcb + 8);
                e3 = *(const float4*)(Erow + (kt + 1) * 64 + pcb + 12);
                #pragma unroll
                for (int rep = 0; rep < 2; rep++) {
                    int i = tid + rep * 256;
                    int vr = i >> 3, d0 = (i & 7) * 8;
                    vreg[rep] = *(const uint4*)(V + (size_t)((kt + 1) * 64 + vr) * HD + d0);
                }
            }
            __syncthreads();
            #pragma unroll
            for (int ks = 0; ks < 64; ks += 16) {
                uint32_t af[4];
                af[0] = *(const uint32_t*)&sPb[(r0    ) * 72 + ks     + 2 * t4];
                af[1] = *(const uint32_t*)&sPb[(r0 + 8) * 72 + ks     + 2 * t4];
                af[2] = *(const uint32_t*)&sPb[(r0    ) * 72 + ks + 8 + 2 * t4];
                af[3] = *(const uint32_t*)&sPb[(r0 + 8) * 72 + ks + 8 + 2 * t4];
                #pragma unroll
                for (int nt = 0; nt < 4; nt++) {
                    int n = wn * 32 + nt * 8 + g;
                    uint32_t bf2[2];
                    bf2[0] = *(const uint32_t*)&sVtb[n * 72 + ks     + 2 * t4];
                    bf2[1] = *(const uint32_t*)&sVtb[n * 72 + ks + 8 + 2 * t4];
                    mma_bf16(acc[nt], af, bf2);
                }
            }
        }

        const int b = bh >> 4, h = bh & 15;
        #pragma unroll
        for (int nt = 0; nt < 4; nt++) {
            int dcol = wn * 32 + nt * 8 + 2 * t4;
            #pragma unroll
            for (int hf = 0; hf < 2; hf++) {
                int trow = q0 + r0 + hf * 8;
                __nv_bfloat162 pr;
                pr.x = __float2bfloat16(acc[nt][hf * 2 + 0]);
                pr.y = __float2bfloat16(acc[nt][hf * 2 + 1]);
                *(__nv_bfloat162*)(g_y + (size_t)(b * TT + trow) * CC + h * HD + dcol) = pr;
            }
        }
    }
}

// ------------------------- launch ---------------------------------------------
extern "C" void kernel_launch(void* const* d_in, const int* in_sizes, int n_in,
                              void* d_out, int out_size)
{
    (void)in_sizes; (void)n_in; (void)out_size;
    const float* x  = (const float*)d_in[0];
    const float* Wq = (const float*)d_in[1];
    const float* bq = (const float*)d_in[2];
    const float* Wk = (const float*)d_in[3];
    const float* bk = (const float*)d_in[4];
    const float* Wv = (const float*)d_in[5];
    const float* bv = (const float*)d_in[6];
    const float* Wo = (const float*)d_in[7];
    const float* bo = (const float*)d_in[8];
    float* out = (float*)d_out;

    cudaFuncSetAttribute(k_gemm, cudaFuncAttributeMaxDynamicSharedMemorySize, GSMEM);

    k_conv_x  <<<(size_t)MM * CC / 1024, 256>>>(x);
    k_prepW   <<<dim3(32, 32, 4), dim3(32, 8)>>>(Wq, Wk, Wv, Wo);
    k_biasprep<<<4, 1024>>>(bq, bk, bv, bo);
    k_rope    <<<TT, 32>>>();
    k_gemm    <<<dim3(8, 64, 3), 256, GSMEM>>>(0, nullptr);   // q,k,v projections (+rope)
    k_att     <<<dim3(32, 64), 256>>>();                      // fused attention
    k_gemm    <<<dim3(8, 64, 1), 256, GSMEM>>>(3, out);       // output projection
}

// round 11
// speedup vs baseline: 1.1526x; 1.1526x over previous
#include <cuda_runtime.h>
#include <cuda_bf16.h>
#include <cstdint>
#include <math.h>

#define BB 4
#define TT 2048
#define CC 1024
#define HH 16
#define HD 64
#define BH (BB*HH)   /* 64 */
#define MM (BB*TT)   /* 8192 */

// ------------------------- scratch (static device globals; no allocs) ---------
__device__ __nv_bfloat16 g_xb[(size_t)MM*CC];          // x in bf16
__device__ __nv_bfloat16 g_WT[4][(size_t)CC*CC];       // Wq,Wk,Wv,Wo transposed [n][k] bf16
__device__ __nv_bfloat16 g_bias[4][CC];                // bq,bk,bv,bo bf16
__device__ __nv_bfloat16 g_q[(size_t)BH*TT*HD];        // [bh][t][d] post-rope bf16
__device__ __nv_bfloat16 g_k[(size_t)BH*TT*HD];
__device__ __nv_bfloat16 g_v[(size_t)BH*TT*HD];
__device__ __nv_bfloat16 g_S[(size_t)BH*TT*TT];        // bf16 scaled logits (lower-tri tiles)
__device__ __nv_bfloat16 g_y[(size_t)MM*CC];           // attention output bf16 [b*T+t][h*64+d]
__device__ float         g_cos[TT*(HD/2)];
__device__ float         g_sin[TT*(HD/2)];

// ------------------------- accurate f32 exp (cephes/Eigen pexp style) ---------
__device__ __forceinline__ float exp_rn(float x) {
    x = fmaxf(x, -87.0f);
    float mf = floorf(__fmaf_rn(x, 1.44269504088896341f, 0.5f));
    float r  = __fmaf_rn(mf, -0.693359375f, x);
    r        = __fmaf_rn(mf,  2.12194440e-4f, r);
    float p  = 1.9875691500e-4f;
    p = __fmaf_rn(p, r, 1.3981999507e-3f);
    p = __fmaf_rn(p, r, 8.3334519073e-3f);
    p = __fmaf_rn(p, r, 4.1665795894e-2f);
    p = __fmaf_rn(p, r, 1.6666665459e-1f);
    p = __fmaf_rn(p, r, 5.0000001201e-1f);
    float y = __fmaf_rn(p, __fmul_rn(r, r), r);
    y = __fadd_rn(y, 1.0f);
    int mi = (int)mf;
    float sc = __int_as_float((mi + 127) << 23);
    return __fmul_rn(y, sc);
}

// ------------------------- mma.sync m16n8k16 bf16 -----------------------------
__device__ __forceinline__ void mma_bf16(float c[4], const uint32_t a[4], const uint32_t b[2]) {
    asm volatile(
        "mma.sync.aligned.m16n8k16.row.col.f32.bf16.bf16.f32 "
        "{%0,%1,%2,%3}, {%4,%5,%6,%7}, {%8,%9}, {%0,%1,%2,%3};\n"
        : "+f"(c[0]), "+f"(c[1]), "+f"(c[2]), "+f"(c[3])
        : "r"(a[0]), "r"(a[1]), "r"(a[2]), "r"(a[3]), "r"(b[0]), "r"(b[1]));
}

// ------------------------- prep kernels ---------------------------------------
__global__ void k_conv_x(const float* __restrict__ x) {
    size_t i = ((size_t)blockIdx.x * 256 + threadIdx.x) * 4;
    float4 v = *(const float4*)(x + i);
    __nv_bfloat162 a, b;
    a.x = __float2bfloat16(v.x); a.y = __float2bfloat16(v.y);
    b.x = __float2bfloat16(v.z); b.y = __float2bfloat16(v.w);
    *(__nv_bfloat162*)(g_xb + i)     = a;
    *(__nv_bfloat162*)(g_xb + i + 2) = b;
}

__global__ void k_prepW(const float* __restrict__ Wq, const float* __restrict__ Wk,
                        const float* __restrict__ Wv, const float* __restrict__ Wo) {
    const float* W = (blockIdx.z == 0) ? Wq : (blockIdx.z == 1) ? Wk : (blockIdx.z == 2) ? Wv : Wo;
    __shared__ float tile[32][33];
    int n0 = blockIdx.x * 32, k0 = blockIdx.y * 32;
    for (int jj = threadIdx.y; jj < 32; jj += 8)
        tile[jj][threadIdx.x] = W[(size_t)(k0 + jj) * CC + n0 + threadIdx.x];
    __syncthreads();
    for (int jj = threadIdx.y; jj < 32; jj += 8)
        g_WT[blockIdx.z][(size_t)(n0 + jj) * CC + k0 + threadIdx.x] =
            __float2bfloat16(tile[threadIdx.x][jj]);
}

__global__ void k_biasprep(const float* __restrict__ bq, const float* __restrict__ bk,
                           const float* __restrict__ bv, const float* __restrict__ bo) {
    const float* p = (blockIdx.x == 0) ? bq : (blockIdx.x == 1) ? bk : (blockIdx.x == 2) ? bv : bo;
    g_bias[blockIdx.x][threadIdx.x] = __float2bfloat16(p[threadIdx.x]);
}

__global__ void k_rope() {
    int t = blockIdx.x, j = threadIdx.x;                 // j in 0..31
    double e = (double)(2 * j) / 64.0;
    float p32 = (float)pow(10000.0, e);                  // f32 rounding of pow
    float inv = __fdiv_rn(1.0f, p32);                    // f32 reciprocal
    float ang = __fmul_rn((float)t, inv);                // f32 angle
    g_cos[t * (HD/2) + j] = (float)cos((double)ang);
    g_sin[t * (HD/2) + j] = (float)sin((double)ang);
}

// ------------------------- GEMM: x@W (+bias, rope) / y@Wo --------------------
// 128x128 tile, k-tile 64, cp.async 2-stage pipeline (R9 config), 256 threads.
#define GSTAGE 36864              /* bytes per stage: (A 128*72 + B 128*72) * 2B */
#define GSMEM  (2*GSTAGE)

__global__ __launch_bounds__(256) void k_gemm(int mode_base, float* __restrict__ outF)
{
    extern __shared__ unsigned char gsm[];
    const int mode = mode_base + blockIdx.z;             // 0=q 1=k 2=v 3=out-proj
    const __nv_bfloat16* __restrict__ A  = (mode < 3) ? g_xb : g_y;
    const __nv_bfloat16* __restrict__ Bt = g_WT[mode];
    const __nv_bfloat16* __restrict__ bs = g_bias[mode];
    const int m0 = blockIdx.y * 128;
    const int n0 = blockIdx.x * 128;

    const int tid = threadIdx.x;
    const int wid = tid >> 5, lane = tid & 31;
    const int g = lane >> 2, t4 = lane & 3;
    const int wm = wid & 3, wn = wid >> 2;

    float acc[16][4];
    #pragma unroll
    for (int i = 0; i < 16; i++) { acc[i][0] = acc[i][1] = acc[i][2] = acc[i][3] = 0.f; }

    {
        __nv_bfloat16* sA = (__nv_bfloat16*)gsm;
        __nv_bfloat16* sB = (__nv_bfloat16*)(gsm + GSTAGE / 2);
        #pragma unroll
        for (int rep = 0; rep < 4; rep++) {
            int i = tid + rep * 256;
            int row = i >> 3, cg = i & 7;
            uint32_t da = (uint32_t)__cvta_generic_to_shared(sA + row * 72 + cg * 8);
            uint32_t db = (uint32_t)__cvta_generic_to_shared(sB + row * 72 + cg * 8);
            asm volatile("cp.async.cg.shared.global [%0], [%1], 16;\n"
                         :: "r"(da), "l"(A  + (size_t)(m0 + row) * CC + cg * 8));
            asm volatile("cp.async.cg.shared.global [%0], [%1], 16;\n"
                         :: "r"(db), "l"(Bt + (size_t)(n0 + row) * CC + cg * 8));
        }
        asm volatile("cp.async.commit_group;\n");
    }

    for (int it = 0; it < 16; it++) {
        asm volatile("cp.async.wait_group 0;\n");
        __syncthreads();
        if (it + 1 < 16) {
            int k0 = (it + 1) * 64;
            unsigned char* stg = gsm + ((it + 1) & 1) * GSTAGE;
            __nv_bfloat16* sA = (__nv_bfloat16*)stg;
            __nv_bfloat16* sB = (__nv_bfloat16*)(stg + GSTAGE / 2);
            #pragma unroll
            for (int rep = 0; rep < 4; rep++) {
                int i = tid + rep * 256;
                int row = i >> 3, cg = i & 7;
                uint32_t da = (uint32_t)__cvta_generic_to_shared(sA + row * 72 + cg * 8);
                uint32_t db = (uint32_t)__cvta_generic_to_shared(sB + row * 72 + cg * 8);
                asm volatile("cp.async.cg.shared.global [%0], [%1], 16;\n"
                             :: "r"(da), "l"(A  + (size_t)(m0 + row) * CC + k0 + cg * 8));
                asm volatile("cp.async.cg.shared.global [%0], [%1], 16;\n"
                             :: "r"(db), "l"(Bt + (size_t)(n0 + row) * CC + k0 + cg * 8));
            }
            asm volatile("cp.async.commit_group;\n");
        }
        const __nv_bfloat16* sA = (const __nv_bfloat16*)(gsm + (it & 1) * GSTAGE);
        const __nv_bfloat16* sB = (const __nv_bfloat16*)(gsm + (it & 1) * GSTAGE + GSTAGE / 2);
        #pragma unroll
        for (int ks = 0; ks < 64; ks += 16) {
            uint32_t af[2][4];
            #pragma unroll
            for (int mt = 0; mt < 2; mt++) {
                int r = wm * 32 + mt * 16 + g;
                af[mt][0] = *(const uint32_t*)&sA[(r    ) * 72 + ks     + 2 * t4];
                af[mt][1] = *(const uint32_t*)&sA[(r + 8) * 72 + ks     + 2 * t4];
                af[mt][2] = *(const uint32_t*)&sA[(r    ) * 72 + ks + 8 + 2 * t4];
                af[mt][3] = *(const uint32_t*)&sA[(r + 8) * 72 + ks + 8 + 2 * t4];
            }
            uint32_t bfr[8][2];
            #pragma unroll
            for (int nt = 0; nt < 8; nt++) {
                int n = wn * 64 + nt * 8 + g;
                bfr[nt][0] = *(const uint32_t*)&sB[n * 72 + ks     + 2 * t4];
                bfr[nt][1] = *(const uint32_t*)&sB[n * 72 + ks + 8 + 2 * t4];
            }
            #pragma unroll
            for (int mt = 0; mt < 2; mt++)
                #pragma unroll
                for (int nt = 0; nt < 8; nt++)
                    mma_bf16(acc[mt * 8 + nt], af[mt], bfr[nt]);
        }
    }

    #pragma unroll
    for (int mt = 0; mt < 2; mt++) {
        #pragma unroll
        for (int nt = 0; nt < 8; nt++) {
            float* c = acc[mt * 8 + nt];
            int col = n0 + wn * 64 + nt * 8 + 2 * t4;
            int r0  = m0 + wm * 32 + mt * 16 + g;
            #pragma unroll
            for (int hf = 0; hf < 2; hf++) {
                int row = r0 + hf * 8;
                __nv_bfloat16 eb = __hadd(__float2bfloat16(c[hf * 2 + 0]), bs[col]);
                __nv_bfloat16 ob = __hadd(__float2bfloat16(c[hf * 2 + 1]), bs[col + 1]);
                if (mode == 3) {
                    outF[(size_t)row * CC + col]     = __bfloat162float(eb);
                    outF[(size_t)row * CC + col + 1] = __bfloat162float(ob);
                } else {
                    int b = row >> 11, t = row & (TT - 1);
                    int h = col >> 6,  d = col & 63;
                    size_t oidx = ((size_t)(b * HH + h) * TT + t) * HD + d;
                    __nv_bfloat162 pr;
                    if (mode <= 1) {                         // rope for q,k
                        int j = d >> 1;
                        float cth = g_cos[t * (HD/2) + j], sth = g_sin[t * (HD/2) + j];
                        float ef = __bfloat162float(eb), of = __bfloat162float(ob);
                        float re = __fsub_rn(__fmul_rn(ef, cth), __fmul_rn(of, sth));
                        float ro = __fadd_rn(__fmul_rn(ef, sth), __fmul_rn(of, cth));
                        pr.x = __float2bfloat16(re);
                        pr.y = __float2bfloat16(ro);
                    } else {
                        pr.x = eb; pr.y = ob;
                    }
                    __nv_bfloat16* outp = (mode == 0) ? g_q : (mode == 1) ? g_k : g_v;
                    *(__nv_bfloat162*)(outp + oidx) = pr;
                }
            }
        }
    }
}

// --------- fused attention: QK^T + max + l (phase A) then softmax@V (phase B) --
// smem overlay: phase A {sQ, sK[2]} and phase B {sP[2], sV[2]} share one buffer.
__global__ __launch_bounds__(256) void k_att()
{
    __shared__ __align__(16) unsigned char buf[36864];
    __shared__ float sMax[2][64];
    __shared__ float sMfin[64];
    __shared__ float sLfin[64];

    const int qt = gridDim.x - 1 - blockIdx.x;           // heavy tiles first
    const int bh = blockIdx.y;
    const int q0 = qt * 64;
    const __nv_bfloat16* __restrict__ Q = g_q + (size_t)bh * TT * HD;
    const __nv_bfloat16* __restrict__ K = g_k + (size_t)bh * TT * HD;
    const __nv_bfloat16* __restrict__ V = g_v + (size_t)bh * TT * HD;

    const int tid = threadIdx.x;
    const int wid = tid >> 5, lane = tid & 31;
    const int g = lane >> 2, t4 = lane & 3;
    const int wm = wid & 3, wn = wid >> 2;
    const int r0 = wm * 16 + g;

    // ===================== phase A: S = bf16(QK^T)*0.125, max, l ==============
    {
        __nv_bfloat16* sQ = (__nv_bfloat16*)buf;                     // 9216 B
        #pragma unroll
        for (int rep = 0; rep < 2; rep++) {
            int i = tid + rep * 256;
            int row = i >> 3, cg = i & 7;
            *(uint4*)&sQ[row * 72 + cg * 8] = *(const uint4*)(Q + (size_t)(q0 + row) * HD + cg * 8);
        }
        // prestage K tile 0
        #pragma unroll
        for (int rep = 0; rep < 2; rep++) {
            int i = tid + rep * 256;
            int row = i >> 3, cg = i & 7;
            uint32_t dst = (uint32_t)__cvta_generic_to_shared(buf + 9216 + (row * 72 + cg * 8) * 2);
            asm volatile("cp.async.cg.shared.global [%0], [%1], 16;\n"
                         :: "r"(dst), "l"(K + (size_t)row * HD + cg * 8));
        }
        asm volatile("cp.async.commit_group;\n");

        const int qg0 = q0 + r0, qg1 = qg0 + 8;
        float rmax0 = -INFINITY, rmax1 = -INFINITY;

        for (int kt = 0; kt <= qt; kt++) {
            asm volatile("cp.async.wait_group 0;\n");
            __syncthreads();
            if (kt < qt) {
                unsigned char* dstb = buf + 9216 + ((kt + 1) & 1) * 9216;
                #pragma unroll
                for (int rep = 0; rep < 2; rep++) {
                    int i = tid + rep * 256;
                    int row = i >> 3, cg = i & 7;
                    uint32_t dst = (uint32_t)__cvta_generic_to_shared(dstb + (row * 72 + cg * 8) * 2);
                    asm volatile("cp.async.cg.shared.global [%0], [%1], 16;\n"
                                 :: "r"(dst), "l"(K + (size_t)((kt + 1) * 64 + row) * HD + cg * 8));
                }
                asm volatile("cp.async.commit_group;\n");
            }
            const __nv_bfloat16* sKb = (const __nv_bfloat16*)(buf + 9216 + (kt & 1) * 9216);
            float acc[4][4] = {};
            #pragma unroll
            for (int ks = 0; ks < 64; ks += 16) {
                uint32_t af[4];
                af[0] = *(const uint32_t*)&sQ[(r0    ) * 72 + ks     + 2 * t4];
                af[1] = *(const uint32_t*)&sQ[(r0 + 8) * 72 + ks     + 2 * t4];
                af[2] = *(const uint32_t*)&sQ[(r0    ) * 72 + ks + 8 + 2 * t4];
                af[3] = *(const uint32_t*)&sQ[(r0 + 8) * 72 + ks + 8 + 2 * t4];
                #pragma unroll
                for (int nt = 0; nt < 4; nt++) {
                    int n = wn * 32 + nt * 8 + g;
                    uint32_t bf2[2];
                    bf2[0] = *(const uint32_t*)&sKb[n * 72 + ks     + 2 * t4];
                    bf2[1] = *(const uint32_t*)&sKb[n * 72 + ks + 8 + 2 * t4];
                    mma_bf16(acc[nt], af, bf2);
                }
            }
            #pragma unroll
            for (int nt = 0; nt < 4; nt++) {
                int cl = wn * 32 + nt * 8 + 2 * t4;
                int kc = kt * 64 + cl;
                {
                    float s0 = __fmul_rn(__bfloat162float(__float2bfloat16(acc[nt][0])), 0.125f);
                    float s1 = __fmul_rn(__bfloat162float(__float2bfloat16(acc[nt][1])), 0.125f);
                    if (kc     <= qg0) rmax0 = fmaxf(rmax0, s0);
                    if (kc + 1 <= qg0) rmax0 = fmaxf(rmax0, s1);
                    __nv_bfloat162 pr; pr.x = __float2bfloat16(s0); pr.y = __float2bfloat16(s1);
                    *(__nv_bfloat162*)(g_S + (size_t)(bh * TT + qg0) * TT + kc) = pr;
                }
                {
                    float s0 = __fmul_rn(__bfloat162float(__float2bfloat16(acc[nt][2])), 0.125f);
                    float s1 = __fmul_rn(__bfloat162float(__float2bfloat16(acc[nt][3])), 0.125f);
                    if (kc     <= qg1) rmax1 = fmaxf(rmax1, s0);
                    if (kc + 1 <= qg1) rmax1 = fmaxf(rmax1, s1);
                    __nv_bfloat162 pr; pr.x = __float2bfloat16(s0); pr.y = __float2bfloat16(s1);
                    *(__nv_bfloat162*)(g_S + (size_t)(bh * TT + qg1) * TT + kc) = pr;
                }
            }
        }
        rmax0 = fmaxf(rmax0, __shfl_xor_sync(0xffffffffu, rmax0, 1));
        rmax0 = fmaxf(rmax0, __shfl_xor_sync(0xffffffffu, rmax0, 2));
        rmax1 = fmaxf(rmax1, __shfl_xor_sync(0xffffffffu, rmax1, 1));
        rmax1 = fmaxf(rmax1, __shfl_xor_sync(0xffffffffu, rmax1, 2));
        if (t4 == 0) {
            sMax[wn][wm * 16 + g]     = rmax0;
            sMax[wn][wm * 16 + g + 8] = rmax1;
        }
        __syncthreads();
        if (tid < 64) sMfin[tid] = fmaxf(sMax[0][tid], sMax[1][tid]);
        __syncthreads();   // S stripe writes + sMfin visible block-wide

        // l-pass over own stripe (L2-hot), op-for-op identical to R8/R9
        {
            const int prow = tid >> 2;
            const int pcb  = (tid & 3) * 16;
            const int qgp  = q0 + prow;
            const float mrow = sMfin[prow];
            const __nv_bfloat16* __restrict__ Srow = g_S + (size_t)(bh * TT + qgp) * TT;
            float lp = 0.f;
            uint4 c0 = *(const uint4*)(Srow + pcb);
            uint4 c1 = *(const uint4*)(Srow + pcb + 8);
            for (int kt = 0; kt <= qt; kt++) {
                uint4 n0v, n1v;
                if (kt < qt) {
                    n0v = *(const uint4*)(Srow + (kt + 1) * 64 + pcb);
                    n1v = *(const uint4*)(Srow + (kt + 1) * 64 + pcb + 8);
                }
                __nv_bfloat16 hv[16];
                *(uint4*)&hv[0] = c0;
                *(uint4*)&hv[8] = c1;
                #pragma unroll
                for (int j = 0; j < 16; j++) {
                    int col = kt * 64 + pcb + j;
                    if (col <= qgp)
                        lp = __fadd_rn(lp, exp_rn(__fsub_rn(__bfloat162float(hv[j]), mrow)));
                }
                c0 = n0v; c1 = n1v;
            }
            lp = __fadd_rn(lp, __shfl_xor_sync(0xffffffffu, lp, 1));
            lp = __fadd_rn(lp, __shfl_xor_sync(0xffffffffu, lp, 2));
            if ((tid & 3) == 0) sLfin[qgp - q0] = lp;
        }
    }
    __syncthreads();   // sLfin ready; phase A smem (sQ/sK) dead from here

    // ===================== phase B: p = bf16(softmax), y = P@V^T ===============
    // V staged UNTRANSPOSED [kseq][72] via cp.async; B-fragments via ldmatrix.trans.
    {
        const int prow = tid >> 2;
        const int pcb  = (tid & 3) * 16;
        const int qgp  = q0 + prow;
        const float mrow = sMfin[prow];
        const float lrow = sLfin[prow];
        const __nv_bfloat16* __restrict__ Srow = g_S + (size_t)(bh * TT + qgp) * TT;

        float acc[4][4] = {};
        const int l16 = lane & 15;

        // prolog: prefetch S chunk(kt=0) into regs; prestage V tile 0 via cp.async
        uint4 s0 = *(const uint4*)(Srow + pcb);
        uint4 s1 = *(const uint4*)(Srow + pcb + 8);
        #pragma unroll
        for (int rep = 0; rep < 2; rep++) {
            int i = tid + rep * 256;
            int row = i >> 3, cg = i & 7;
            uint32_t dst = (uint32_t)__cvta_generic_to_shared(buf + 18432 + (row * 72 + cg * 8) * 2);
            asm volatile("cp.async.cg.shared.global [%0], [%1], 16;\n"
                         :: "r"(dst), "l"(V + (size_t)row * HD + cg * 8));
        }
        asm volatile("cp.async.commit_group;\n");

        for (int kt = 0; kt <= qt; kt++) {
            const int bsel = kt & 1;
            __nv_bfloat16* sPb = (__nv_bfloat16*)(buf + bsel * 9216);
            const __nv_bfloat16* sVb = (const __nv_bfloat16*)(buf + 18432 + bsel * 9216);
            // probabilities from prefetched S regs (bf16, reference rounding)
            {
                __nv_bfloat16 hv[16];
                *(uint4*)&hv[0] = s0;
                *(uint4*)&hv[8] = s1;
                #pragma unroll
                for (int j = 0; j < 16; j += 2) {
                    int col = kt * 64 + pcb + j;
                    __nv_bfloat162 pr;
                    pr.x = (col     <= qgp)
                         ? __float2bfloat16(__fdiv_rn(exp_rn(__fsub_rn(__bfloat162float(hv[j]),     mrow)), lrow))
                         : __float2bfloat16(0.f);
                    pr.y = (col + 1 <= qgp)
                         ? __float2bfloat16(__fdiv_rn(exp_rn(__fsub_rn(__bfloat162float(hv[j + 1]), mrow)), lrow))
                         : __float2bfloat16(0.f);
                    *(__nv_bfloat162*)&sPb[prow * 72 + pcb + j] = pr;
                }
            }
            asm volatile("cp.async.wait_group 0;\n");
            __syncthreads();            // sP[bsel] + V(kt) visible; prev mma done
            if (kt < qt) {
                unsigned char* dstb = buf + 18432 + ((kt + 1) & 1) * 9216;
                #pragma unroll
                for (int rep = 0; rep < 2; rep++) {
                    int i = tid + rep * 256;
                    int row = i >> 3, cg = i & 7;
                    uint32_t dst = (uint32_t)__cvta_generic_to_shared(dstb + (row * 72 + cg * 8) * 2);
                    asm volatile("cp.async.cg.shared.global [%0], [%1], 16;\n"
                                 :: "r"(dst), "l"(V + (size_t)((kt + 1) * 64 + row) * HD + cg * 8));
                }
                asm volatile("cp.async.commit_group;\n");
                s0 = *(const uint4*)(Srow + (kt + 1) * 64 + pcb);
                s1 = *(const uint4*)(Srow + (kt + 1) * 64 + pcb + 8);
            }
            #pragma unroll
            for (int ks = 0; ks < 64; ks += 16) {
                uint32_t af[4];
                af[0] = *(const uint32_t*)&sPb[(r0    ) * 72 + ks     + 2 * t4];
                af[1] = *(const uint32_t*)&sPb[(r0 + 8) * 72 + ks     + 2 * t4];
                af[2] = *(const uint32_t*)&sPb[(r0    ) * 72 + ks + 8 + 2 * t4];
                af[3] = *(const uint32_t*)&sPb[(r0 + 8) * 72 + ks + 8 + 2 * t4];
                #pragma unroll
                for (int nt = 0; nt < 4; nt++) {
                    int n0c = wn * 32 + nt * 8;
                    uint32_t vaddr = (uint32_t)__cvta_generic_to_shared(
                        sVb + (size_t)(ks + l16) * 72 + n0c);
                    uint32_t b2[2];
                    asm volatile(
                        "ldmatrix.sync.aligned.m8n8.x2.trans.shared.b16 {%0,%1}, [%2];"
                        : "=r"(b2[0]), "=r"(b2[1]) : "r"(vaddr));
                    mma_bf16(acc[nt], af, b2);
                }
            }
        }

        const int b = bh >> 4, h = bh & 15;
        #pragma unroll
        for (int nt = 0; nt < 4; nt++) {
            int dcol = wn * 32 + nt * 8 + 2 * t4;
            #pragma unroll
            for (int hf = 0; hf < 2; hf++) {
                int trow = q0 + r0 + hf * 8;
                __nv_bfloat162 pr;
                pr.x = __float2bfloat16(acc[nt][hf * 2 + 0]);
                pr.y = __float2bfloat16(acc[nt][hf * 2 + 1]);
                *(__nv_bfloat162*)(g_y + (size_t)(b * TT + trow) * CC + h * HD + dcol) = pr;
            }
        }
    }
}

// ------------------------- launch ---------------------------------------------
extern "C" void kernel_launch(void* const* d_in, const int* in_sizes, int n_in,
                              void* d_out, int out_size)
{
    (void)in_sizes; (void)n_in; (void)out_size;
    const float* x  = (const float*)d_in[0];
    const float* Wq = (const float*)d_in[1];
    const float* bq = (const float*)d_in[2];
    const float* Wk = (const float*)d_in[3];
    const float* bk = (const float*)d_in[4];
    const float* Wv = (const float*)d_in[5];
    const float* bv = (const float*)d_in[6];
    const float* Wo = (const float*)d_in[7];
    const float* bo = (const float*)d_in[8];
    float* out = (float*)d_out;

    cudaFuncSetAttribute(k_gemm, cudaFuncAttributeMaxDynamicSharedMemorySize, GSMEM);

    k_conv_x  <<<(size_t)MM * CC / 1024, 256>>>(x);
    k_prepW   <<<dim3(32, 32, 4), dim3(32, 8)>>>(Wq, Wk, Wv, Wo);
    k_biasprep<<<4, 1024>>>(bq, bk, bv, bo);
    k_rope    <<<TT, 32>>>();
    k_gemm    <<<dim3(8, 64, 3), 256, GSMEM>>>(0, nullptr);   // q,k,v projections (+rope)
    k_att     <<<dim3(32, 64), 256>>>();                      // fused attention
    k_gemm    <<<dim3(8, 64, 1), 256, GSMEM>>>(3, out);       // output projection
}

// round 12
// speedup vs baseline: 1.2032x; 1.0439x over previous
#include <cuda_runtime.h>
#include <cuda_bf16.h>
#include <cstdint>
#include <math.h>

#define BB 4
#define TT 2048
#define CC 1024
#define HH 16
#define HD 64
#define BH (BB*HH)   /* 64 */
#define MM (BB*TT)   /* 8192 */

// ------------------------- scratch (static device globals; no allocs) ---------
__device__ __nv_bfloat16 g_xb[(size_t)MM*CC];          // x in bf16
__device__ __nv_bfloat16 g_WT[4][(size_t)CC*CC];       // Wq,Wk,Wv,Wo transposed [n][k] bf16
__device__ __nv_bfloat16 g_bias[4][CC];                // bq,bk,bv,bo bf16
__device__ __nv_bfloat16 g_q[(size_t)BH*TT*HD];        // [bh][t][d] post-rope bf16
__device__ __nv_bfloat16 g_k[(size_t)BH*TT*HD];
__device__ __nv_bfloat16 g_v[(size_t)BH*TT*HD];
__device__ __nv_bfloat16 g_S[(size_t)BH*TT*TT];        // bf16 scaled logits (lower-tri tiles)
__device__ __nv_bfloat16 g_y[(size_t)MM*CC];           // attention output bf16 [b*T+t][h*64+d]
__device__ float         g_cos[TT*(HD/2)];
__device__ float         g_sin[TT*(HD/2)];

// ------------------------- accurate f32 exp (cephes/Eigen pexp style) ---------
__device__ __forceinline__ float exp_rn(float x) {
    x = fmaxf(x, -87.0f);
    float mf = floorf(__fmaf_rn(x, 1.44269504088896341f, 0.5f));
    float r  = __fmaf_rn(mf, -0.693359375f, x);
    r        = __fmaf_rn(mf,  2.12194440e-4f, r);
    float p  = 1.9875691500e-4f;
    p = __fmaf_rn(p, r, 1.3981999507e-3f);
    p = __fmaf_rn(p, r, 8.3334519073e-3f);
    p = __fmaf_rn(p, r, 4.1665795894e-2f);
    p = __fmaf_rn(p, r, 1.6666665459e-1f);
    p = __fmaf_rn(p, r, 5.0000001201e-1f);
    float y = __fmaf_rn(p, __fmul_rn(r, r), r);
    y = __fadd_rn(y, 1.0f);
    int mi = (int)mf;
    float sc = __int_as_float((mi + 127) << 23);
    return __fmul_rn(y, sc);
}

// ------------------------- mma.sync m16n8k16 bf16 -----------------------------
__device__ __forceinline__ void mma_bf16(float c[4], const uint32_t a[4], const uint32_t b[2]) {
    asm volatile(
        "mma.sync.aligned.m16n8k16.row.col.f32.bf16.bf16.f32 "
        "{%0,%1,%2,%3}, {%4,%5,%6,%7}, {%8,%9}, {%0,%1,%2,%3};\n"
        : "+f"(c[0]), "+f"(c[1]), "+f"(c[2]), "+f"(c[3])
        : "r"(a[0]), "r"(a[1]), "r"(a[2]), "r"(a[3]), "r"(b[0]), "r"(b[1]));
}

__device__ __forceinline__ void ldsm_x4(uint32_t r[4], uint32_t addr) {
    asm volatile("ldmatrix.sync.aligned.m8n8.x4.shared.b16 {%0,%1,%2,%3}, [%4];"
                 : "=r"(r[0]), "=r"(r[1]), "=r"(r[2]), "=r"(r[3]) : "r"(addr));
}

// ------------------------- prep kernels ---------------------------------------
__global__ void k_conv_x(const float* __restrict__ x) {
    size_t i = ((size_t)blockIdx.x * 256 + threadIdx.x) * 4;
    float4 v = *(const float4*)(x + i);
    __nv_bfloat162 a, b;
    a.x = __float2bfloat16(v.x); a.y = __float2bfloat16(v.y);
    b.x = __float2bfloat16(v.z); b.y = __float2bfloat16(v.w);
    *(__nv_bfloat162*)(g_xb + i)     = a;
    *(__nv_bfloat162*)(g_xb + i + 2) = b;
}

__global__ void k_prepW(const float* __restrict__ Wq, const float* __restrict__ Wk,
                        const float* __restrict__ Wv, const float* __restrict__ Wo) {
    const float* W = (blockIdx.z == 0) ? Wq : (blockIdx.z == 1) ? Wk : (blockIdx.z == 2) ? Wv : Wo;
    __shared__ float tile[32][33];
    int n0 = blockIdx.x * 32, k0 = blockIdx.y * 32;
    for (int jj = threadIdx.y; jj < 32; jj += 8)
        tile[jj][threadIdx.x] = W[(size_t)(k0 + jj) * CC + n0 + threadIdx.x];
    __syncthreads();
    for (int jj = threadIdx.y; jj < 32; jj += 8)
        g_WT[blockIdx.z][(size_t)(n0 + jj) * CC + k0 + threadIdx.x] =
            __float2bfloat16(tile[threadIdx.x][jj]);
}

__global__ void k_biasprep(const float* __restrict__ bq, const float* __restrict__ bk,
                           const float* __restrict__ bv, const float* __restrict__ bo) {
    const float* p = (blockIdx.x == 0) ? bq : (blockIdx.x == 1) ? bk : (blockIdx.x == 2) ? bv : bo;
    g_bias[blockIdx.x][threadIdx.x] = __float2bfloat16(p[threadIdx.x]);
}

__global__ void k_rope() {
    int t = blockIdx.x, j = threadIdx.x;                 // j in 0..31
    double e = (double)(2 * j) / 64.0;
    float p32 = (float)pow(10000.0, e);                  // f32 rounding of pow
    float inv = __fdiv_rn(1.0f, p32);                    // f32 reciprocal
    float ang = __fmul_rn((float)t, inv);                // f32 angle
    g_cos[t * (HD/2) + j] = (float)cos((double)ang);
    g_sin[t * (HD/2) + j] = (float)sin((double)ang);
}

// ------------------------- GEMM: x@W (+bias, rope) / y@Wo --------------------
// 128x128 tile, k-tile 64, cp.async 2-stage pipeline, ldmatrix fragment loads.
#define GSTAGE 36864              /* bytes per stage: (A 128*72 + B 128*72) * 2B */
#define GSMEM  (2*GSTAGE)

__global__ __launch_bounds__(256) void k_gemm(int mode_base, float* __restrict__ outF)
{
    extern __shared__ unsigned char gsm[];
    const int mode = mode_base + blockIdx.z;             // 0=q 1=k 2=v 3=out-proj
    const __nv_bfloat16* __restrict__ A  = (mode < 3) ? g_xb : g_y;
    const __nv_bfloat16* __restrict__ Bt = g_WT[mode];
    const __nv_bfloat16* __restrict__ bs = g_bias[mode];
    const int m0 = blockIdx.y * 128;
    const int n0 = blockIdx.x * 128;

    const int tid = threadIdx.x;
    const int wid = tid >> 5, lane = tid & 31;
    const int g = lane >> 2, t4 = lane & 3;
    const int wm = wid & 3, wn = wid >> 2;
    const int lb = lane >> 3, lr = lane & 7;             // ldmatrix block id / row

    float acc[16][4];
    #pragma unroll
    for (int i = 0; i < 16; i++) { acc[i][0] = acc[i][1] = acc[i][2] = acc[i][3] = 0.f; }

    {
        __nv_bfloat16* sA = (__nv_bfloat16*)gsm;
        __nv_bfloat16* sB = (__nv_bfloat16*)(gsm + GSTAGE / 2);
        #pragma unroll
        for (int rep = 0; rep < 4; rep++) {
            int i = tid + rep * 256;
            int row = i >> 3, cg = i & 7;
            uint32_t da = (uint32_t)__cvta_generic_to_shared(sA + row * 72 + cg * 8);
            uint32_t db = (uint32_t)__cvta_generic_to_shared(sB + row * 72 + cg * 8);
            asm volatile("cp.async.cg.shared.global [%0], [%1], 16;\n"
                         :: "r"(da), "l"(A  + (size_t)(m0 + row) * CC + cg * 8));
            asm volatile("cp.async.cg.shared.global [%0], [%1], 16;\n"
                         :: "r"(db), "l"(Bt + (size_t)(n0 + row) * CC + cg * 8));
        }
        asm volatile("cp.async.commit_group;\n");
    }

    for (int it = 0; it < 16; it++) {
        asm volatile("cp.async.wait_group 0;\n");
        __syncthreads();
        if (it + 1 < 16) {
            int k0 = (it + 1) * 64;
            unsigned char* stg = gsm + ((it + 1) & 1) * GSTAGE;
            __nv_bfloat16* sA = (__nv_bfloat16*)stg;
            __nv_bfloat16* sB = (__nv_bfloat16*)(stg + GSTAGE / 2);
            #pragma unroll
            for (int rep = 0; rep < 4; rep++) {
                int i = tid + rep * 256;
                int row = i >> 3, cg = i & 7;
                uint32_t da = (uint32_t)__cvta_generic_to_shared(sA + row * 72 + cg * 8);
                uint32_t db = (uint32_t)__cvta_generic_to_shared(sB + row * 72 + cg * 8);
                asm volatile("cp.async.cg.shared.global [%0], [%1], 16;\n"
                             :: "r"(da), "l"(A  + (size_t)(m0 + row) * CC + k0 + cg * 8));
                asm volatile("cp.async.cg.shared.global [%0], [%1], 16;\n"
                             :: "r"(db), "l"(Bt + (size_t)(n0 + row) * CC + k0 + cg * 8));
            }
            asm volatile("cp.async.commit_group;\n");
        }
        const __nv_bfloat16* sA = (const __nv_bfloat16*)(gsm + (it & 1) * GSTAGE);
        const __nv_bfloat16* sB = (const __nv_bfloat16*)(gsm + (it & 1) * GSTAGE + GSTAGE / 2);
        #pragma unroll
        for (int ks = 0; ks < 64; ks += 16) {
            // A fragments: blocks (rows/+8) x (cols/+8)
            uint32_t af[2][4];
            #pragma unroll
            for (int mt = 0; mt < 2; mt++) {
                int row = wm * 32 + mt * 16 + (lb & 1) * 8 + lr;
                int col = ks + (lb >> 1) * 8;
                ldsm_x4(af[mt], (uint32_t)__cvta_generic_to_shared(sA + row * 72 + col));
            }
            // B fragments: nt pairs, blocks (n-rows nt/nt+1) x (k/k+8)
            uint32_t bfr[8][2];
            #pragma unroll
            for (int p = 0; p < 4; p++) {
                int row = wn * 64 + (2 * p + (lb >> 1)) * 8 + lr;
                int col = ks + (lb & 1) * 8;
                uint32_t q[4];
                ldsm_x4(q, (uint32_t)__cvta_generic_to_shared(sB + row * 72 + col));
                bfr[2 * p][0] = q[0]; bfr[2 * p][1] = q[1];
                bfr[2 * p + 1][0] = q[2]; bfr[2 * p + 1][1] = q[3];
            }
            #pragma unroll
            for (int mt = 0; mt < 2; mt++)
                #pragma unroll
                for (int nt = 0; nt < 8; nt++)
                    mma_bf16(acc[mt * 8 + nt], af[mt], bfr[nt]);
        }
    }

    #pragma unroll
    for (int mt = 0; mt < 2; mt++) {
        #pragma unroll
        for (int nt = 0; nt < 8; nt++) {
            float* c = acc[mt * 8 + nt];
            int col = n0 + wn * 64 + nt * 8 + 2 * t4;
            int r0  = m0 + wm * 32 + mt * 16 + g;
            #pragma unroll
            for (int hf = 0; hf < 2; hf++) {
                int row = r0 + hf * 8;
                __nv_bfloat16 eb = __hadd(__float2bfloat16(c[hf * 2 + 0]), bs[col]);
                __nv_bfloat16 ob = __hadd(__float2bfloat16(c[hf * 2 + 1]), bs[col + 1]);
                if (mode == 3) {
                    outF[(size_t)row * CC + col]     = __bfloat162float(eb);
                    outF[(size_t)row * CC + col + 1] = __bfloat162float(ob);
                } else {
                    int b = row >> 11, t = row & (TT - 1);
                    int h = col >> 6,  d = col & 63;
                    size_t oidx = ((size_t)(b * HH + h) * TT + t) * HD + d;
                    __nv_bfloat162 pr;
                    if (mode <= 1) {                         // rope for q,k
                        int j = d >> 1;
                        float cth = g_cos[t * (HD/2) + j], sth = g_sin[t * (HD/2) + j];
                        float ef = __bfloat162float(eb), of = __bfloat162float(ob);
                        float re = __fsub_rn(__fmul_rn(ef, cth), __fmul_rn(of, sth));
                        float ro = __fadd_rn(__fmul_rn(ef, sth), __fmul_rn(of, cth));
                        pr.x = __float2bfloat16(re);
                        pr.y = __float2bfloat16(ro);
                    } else {
                        pr.x = eb; pr.y = ob;
                    }
                    __nv_bfloat16* outp = (mode == 0) ? g_q : (mode == 1) ? g_k : g_v;
                    *(__nv_bfloat162*)(outp + oidx) = pr;
                }
            }
        }
    }
}

// --------- fused attention: QK^T + max + l (phase A) then softmax@V (phase B) --
__global__ __launch_bounds__(256) void k_att()
{
    __shared__ __align__(16) unsigned char buf[36864];
    __shared__ float sMax[2][64];
    __shared__ float sMfin[64];
    __shared__ float sLfin[64];

    const int qt = gridDim.x - 1 - blockIdx.x;           // heavy tiles first
    const int bh = blockIdx.y;
    const int q0 = qt * 64;
    const __nv_bfloat16* __restrict__ Q = g_q + (size_t)bh * TT * HD;
    const __nv_bfloat16* __restrict__ K = g_k + (size_t)bh * TT * HD;
    const __nv_bfloat16* __restrict__ V = g_v + (size_t)bh * TT * HD;

    const int tid = threadIdx.x;
    const int wid = tid >> 5, lane = tid & 31;
    const int g = lane >> 2, t4 = lane & 3;
    const int wm = wid & 3, wn = wid >> 2;
    const int r0 = wm * 16 + g;
    const int lb = lane >> 3, lr = lane & 7;             // ldmatrix block id / row

    // ===================== phase A: S = bf16(QK^T)*0.125, max, l ==============
    {
        __nv_bfloat16* sQ = (__nv_bfloat16*)buf;                     // 9216 B
        #pragma unroll
        for (int rep = 0; rep < 2; rep++) {
            int i = tid + rep * 256;
            int row = i >> 3, cg = i & 7;
            *(uint4*)&sQ[row * 72 + cg * 8] = *(const uint4*)(Q + (size_t)(q0 + row) * HD + cg * 8);
        }
        // prestage K tile 0
        #pragma unroll
        for (int rep = 0; rep < 2; rep++) {
            int i = tid + rep * 256;
            int row = i >> 3, cg = i & 7;
            uint32_t dst = (uint32_t)__cvta_generic_to_shared(buf + 9216 + (row * 72 + cg * 8) * 2);
            asm volatile("cp.async.cg.shared.global [%0], [%1], 16;\n"
                         :: "r"(dst), "l"(K + (size_t)row * HD + cg * 8));
        }
        asm volatile("cp.async.commit_group;\n");

        const int qg0 = q0 + r0, qg1 = qg0 + 8;
        float rmax0 = -INFINITY, rmax1 = -INFINITY;

        for (int kt = 0; kt <= qt; kt++) {
            asm volatile("cp.async.wait_group 0;\n");
            __syncthreads();
            if (kt < qt) {
                unsigned char* dstb = buf + 9216 + ((kt + 1) & 1) * 9216;
                #pragma unroll
                for (int rep = 0; rep < 2; rep++) {
                    int i = tid + rep * 256;
                    int row = i >> 3, cg = i & 7;
                    uint32_t dst = (uint32_t)__cvta_generic_to_shared(dstb + (row * 72 + cg * 8) * 2);
                    asm volatile("cp.async.cg.shared.global [%0], [%1], 16;\n"
                                 :: "r"(dst), "l"(K + (size_t)((kt + 1) * 64 + row) * HD + cg * 8));
                }
                asm volatile("cp.async.commit_group;\n");
            }
            const __nv_bfloat16* sKb = (const __nv_bfloat16*)(buf + 9216 + (kt & 1) * 9216);
            float acc[4][4] = {};
            #pragma unroll
            for (int ks = 0; ks < 64; ks += 16) {
                uint32_t af[4];
                {
                    int row = wm * 16 + (lb & 1) * 8 + lr;
                    int col = ks + (lb >> 1) * 8;
                    ldsm_x4(af, (uint32_t)__cvta_generic_to_shared(sQ + row * 72 + col));
                }
                uint32_t kf[4][2];
                #pragma unroll
                for (int p = 0; p < 2; p++) {
                    int row = wn * 32 + (2 * p + (lb >> 1)) * 8 + lr;
                    int col = ks + (lb & 1) * 8;
                    uint32_t q4[4];
                    ldsm_x4(q4, (uint32_t)__cvta_generic_to_shared(sKb + row * 72 + col));
                    kf[2 * p][0] = q4[0]; kf[2 * p][1] = q4[1];
                    kf[2 * p + 1][0] = q4[2]; kf[2 * p + 1][1] = q4[3];
                }
                #pragma unroll
                for (int nt = 0; nt < 4; nt++)
                    mma_bf16(acc[nt], af, kf[nt]);
            }
            #pragma unroll
            for (int nt = 0; nt < 4; nt++) {
                int cl = wn * 32 + nt * 8 + 2 * t4;
                int kc = kt * 64 + cl;
                {
                    float s0 = __fmul_rn(__bfloat162float(__float2bfloat16(acc[nt][0])), 0.125f);
                    float s1 = __fmul_rn(__bfloat162float(__float2bfloat16(acc[nt][1])), 0.125f);
                    if (kc     <= qg0) rmax0 = fmaxf(rmax0, s0);
                    if (kc + 1 <= qg0) rmax0 = fmaxf(rmax0, s1);
                    __nv_bfloat162 pr; pr.x = __float2bfloat16(s0); pr.y = __float2bfloat16(s1);
                    *(__nv_bfloat162*)(g_S + (size_t)(bh * TT + qg0) * TT + kc) = pr;
                }
                {
                    float s0 = __fmul_rn(__bfloat162float(__float2bfloat16(acc[nt][2])), 0.125f);
                    float s1 = __fmul_rn(__bfloat162float(__float2bfloat16(acc[nt][3])), 0.125f);
                    if (kc     <= qg1) rmax1 = fmaxf(rmax1, s0);
                    if (kc + 1 <= qg1) rmax1 = fmaxf(rmax1, s1);
                    __nv_bfloat162 pr; pr.x = __float2bfloat16(s0); pr.y = __float2bfloat16(s1);
                    *(__nv_bfloat162*)(g_S + (size_t)(bh * TT + qg1) * TT + kc) = pr;
                }
            }
        }
        rmax0 = fmaxf(rmax0, __shfl_xor_sync(0xffffffffu, rmax0, 1));
        rmax0 = fmaxf(rmax0, __shfl_xor_sync(0xffffffffu, rmax0, 2));
        rmax1 = fmaxf(rmax1, __shfl_xor_sync(0xffffffffu, rmax1, 1));
        rmax1 = fmaxf(rmax1, __shfl_xor_sync(0xffffffffu, rmax1, 2));
        if (t4 == 0) {
            sMax[wn][wm * 16 + g]     = rmax0;
            sMax[wn][wm * 16 + g + 8] = rmax1;
        }
        __syncthreads();
        if (tid < 64) sMfin[tid] = fmaxf(sMax[0][tid], sMax[1][tid]);
        __syncthreads();   // S stripe writes + sMfin visible block-wide

        // l-pass over own stripe (L2-hot), op-for-op identical to R8/R9/R11
        {
            const int prow = tid >> 2;
            const int pcb  = (tid & 3) * 16;
            const int qgp  = q0 + prow;
            const float mrow = sMfin[prow];
            const __nv_bfloat16* __restrict__ Srow = g_S + (size_t)(bh * TT + qgp) * TT;
            float lp = 0.f;
            uint4 c0 = *(const uint4*)(Srow + pcb);
            uint4 c1 = *(const uint4*)(Srow + pcb + 8);
            for (int kt = 0; kt <= qt; kt++) {
                uint4 n0v, n1v;
                if (kt < qt) {
                    n0v = *(const uint4*)(Srow + (kt + 1) * 64 + pcb);
                    n1v = *(const uint4*)(Srow + (kt + 1) * 64 + pcb + 8);
                }
                __nv_bfloat16 hv[16];
                *(uint4*)&hv[0] = c0;
                *(uint4*)&hv[8] = c1;
                #pragma unroll
                for (int j = 0; j < 16; j++) {
                    int col = kt * 64 + pcb + j;
                    if (col <= qgp)
                        lp = __fadd_rn(lp, exp_rn(__fsub_rn(__bfloat162float(hv[j]), mrow)));
                }
                c0 = n0v; c1 = n1v;
            }
            lp = __fadd_rn(lp, __shfl_xor_sync(0xffffffffu, lp, 1));
            lp = __fadd_rn(lp, __shfl_xor_sync(0xffffffffu, lp, 2));
            if ((tid & 3) == 0) sLfin[qgp - q0] = lp;
        }
    }
    __syncthreads();   // sLfin ready; phase A smem (sQ/sK) dead from here

    // ===================== phase B: p = bf16(softmax), y = P@V^T ===============
    // V staged untransposed [kseq][72] via cp.async; B-fragments via ldmatrix.trans.
    {
        const int prow = tid >> 2;
        const int pcb  = (tid & 3) * 16;
        const int qgp  = q0 + prow;
        const float mrow = sMfin[prow];
        const float lrow = sLfin[prow];
        const __nv_bfloat16* __restrict__ Srow = g_S + (size_t)(bh * TT + qgp) * TT;

        float acc[4][4] = {};
        const int l16 = lane & 15;

        // prolog: prefetch S chunk(kt=0) into regs; prestage V tile 0 via cp.async
        uint4 s0 = *(const uint4*)(Srow + pcb);
        uint4 s1 = *(const uint4*)(Srow + pcb + 8);
        #pragma unroll
        for (int rep = 0; rep < 2; rep++) {
            int i = tid + rep * 256;
            int row = i >> 3, cg = i & 7;
            uint32_t dst = (uint32_t)__cvta_generic_to_shared(buf + 18432 + (row * 72 + cg * 8) * 2);
            asm volatile("cp.async.cg.shared.global [%0], [%1], 16;\n"
                         :: "r"(dst), "l"(V + (size_t)row * HD + cg * 8));
        }
        asm volatile("cp.async.commit_group;\n");

        for (int kt = 0; kt <= qt; kt++) {
            const int bsel = kt & 1;
            __nv_bfloat16* sPb = (__nv_bfloat16*)(buf + bsel * 9216);
            const __nv_bfloat16* sVb = (const __nv_bfloat16*)(buf + 18432 + bsel * 9216);
            // probabilities from prefetched S regs (bf16, reference rounding)
            {
                __nv_bfloat16 hv[16];
                *(uint4*)&hv[0] = s0;
                *(uint4*)&hv[8] = s1;
                #pragma unroll
                for (int j = 0; j < 16; j += 2) {
                    int col = kt * 64 + pcb + j;
                    __nv_bfloat162 pr;
                    pr.x = (col     <= qgp)
                         ? __float2bfloat16(__fdiv_rn(exp_rn(__fsub_rn(__bfloat162float(hv[j]),     mrow)), lrow))
                         : __float2bfloat16(0.f);
                    pr.y = (col + 1 <= qgp)
                         ? __float2bfloat16(__fdiv_rn(exp_rn(__fsub_rn(__bfloat162float(hv[j + 1]), mrow)), lrow))
                         : __float2bfloat16(0.f);
                    *(__nv_bfloat162*)&sPb[prow * 72 + pcb + j] = pr;
                }
            }
            asm volatile("cp.async.wait_group 0;\n");
            __syncthreads();            // sP[bsel] + V(kt) visible; prev mma done
            if (kt < qt) {
                unsigned char* dstb = buf + 18432 + ((kt + 1) & 1) * 9216;
                #pragma unroll
                for (int rep = 0; rep < 2; rep++) {
                    int i = tid + rep * 256;
                    int row = i >> 3, cg = i & 7;
                    uint32_t dst = (uint32_t)__cvta_generic_to_shared(dstb + (row * 72 + cg * 8) * 2);
                    asm volatile("cp.async.cg.shared.global [%0], [%1], 16;\n"
                                 :: "r"(dst), "l"(V + (size_t)((kt + 1) * 64 + row) * HD + cg * 8));
                }
                asm volatile("cp.async.commit_group;\n");
                s0 = *(const uint4*)(Srow + (kt + 1) * 64 + pcb);
                s1 = *(const uint4*)(Srow + (kt + 1) * 64 + pcb + 8);
            }
            #pragma unroll
            for (int ks = 0; ks < 64; ks += 16) {
                uint32_t af[4];
                {
                    int row = wm * 16 + (lb & 1) * 8 + lr;
                    int col = ks + (lb >> 1) * 8;
                    ldsm_x4(af, (uint32_t)__cvta_generic_to_shared(sPb + row * 72 + col));
                }
                #pragma unroll
                for (int nt = 0; nt < 4; nt++) {
                    int n0c = wn * 32 + nt * 8;
                    uint32_t vaddr = (uint32_t)__cvta_generic_to_shared(
                        sVb + (size_t)(ks + l16) * 72 + n0c);
                    uint32_t b2[2];
                    asm volatile(
                        "ldmatrix.sync.aligned.m8n8.x2.trans.shared.b16 {%0,%1}, [%2];"
                        : "=r"(b2[0]), "=r"(b2[1]) : "r"(vaddr));
                    mma_bf16(acc[nt], af, b2);
                }
            }
        }

        const int b = bh >> 4, h = bh & 15;
        #pragma unroll
        for (int nt = 0; nt < 4; nt++) {
            int dcol = wn * 32 + nt * 8 + 2 * t4;
            #pragma unroll
            for (int hf = 0; hf < 2; hf++) {
                int trow = q0 + r0 + hf * 8;
                __nv_bfloat162 pr;
                pr.x = __float2bfloat16(acc[nt][hf * 2 + 0]);
                pr.y = __float2bfloat16(acc[nt][hf * 2 + 1]);
                *(__nv_bfloat162*)(g_y + (size_t)(b * TT + trow) * CC + h * HD + dcol) = pr;
            }
        }
    }
}

// ------------------------- launch ---------------------------------------------
extern "C" void kernel_launch(void* const* d_in, const int* in_sizes, int n_in,
                              void* d_out, int out_size)
{
    (void)in_sizes; (void)n_in; (void)out_size;
    const float* x  = (const float*)d_in[0];
    const float* Wq = (const float*)d_in[1];
    const float* bq = (const float*)d_in[2];
    const float* Wk = (const float*)d_in[3];
    const float* bk = (const float*)d_in[4];
    const float* Wv = (const float*)d_in[5];
    const float* bv = (const float*)d_in[6];
    const float* Wo = (const float*)d_in[7];
    const float* bo = (const float*)d_in[8];
    float* out = (float*)d_out;

    cudaFuncSetAttribute(k_gemm, cudaFuncAttributeMaxDynamicSharedMemorySize, GSMEM);

    k_conv_x  <<<(size_t)MM * CC / 1024, 256>>>(x);
    k_prepW   <<<dim3(32, 32, 4), dim3(32, 8)>>>(Wq, Wk, Wv, Wo);
    k_biasprep<<<4, 1024>>>(bq, bk, bv, bo);
    k_rope    <<<TT, 32>>>();
    k_gemm    <<<dim3(8, 64, 3), 256, GSMEM>>>(0, nullptr);   // q,k,v projections (+rope)
    k_att     <<<dim3(32, 64), 256>>>();                      // fused attention
    k_gemm    <<<dim3(8, 64, 1), 256, GSMEM>>>(3, out);       // output projection
}

// round 13
// speedup vs baseline: 1.2751x; 1.0597x over previous
#include <cuda_runtime.h>
#include <cuda_bf16.h>
#include <cstdint>
#include <math.h>

#define BB 4
#define TT 2048
#define CC 1024
#define HH 16
#define HD 64
#define BH (BB*HH)   /* 64 */
#define MM (BB*TT)   /* 8192 */

// ------------------------- scratch (static device globals; no allocs) ---------
__device__ __nv_bfloat16 g_xb[(size_t)MM*CC];          // x in bf16
__device__ __nv_bfloat16 g_WT[4][(size_t)CC*CC];       // Wq,Wk,Wv,Wo transposed [n][k] bf16
__device__ __nv_bfloat16 g_bias[4][CC];                // bq,bk,bv,bo bf16
__device__ __nv_bfloat16 g_q[(size_t)BH*TT*HD];        // [bh][t][d] post-rope bf16
__device__ __nv_bfloat16 g_k[(size_t)BH*TT*HD];
__device__ __nv_bfloat16 g_v[(size_t)BH*TT*HD];
__device__ __nv_bfloat16 g_S[(size_t)BH*TT*TT];        // bf16 scaled logits (lower-tri tiles)
__device__ __nv_bfloat16 g_y[(size_t)MM*CC];           // attention output bf16 [b*T+t][h*64+d]
__device__ float         g_cos[TT*(HD/2)];
__device__ float         g_sin[TT*(HD/2)];

// ------------------------- packed f32x2 primitives (sm_100a) ------------------
// Each packed op = two independent IEEE-RN f32 ops -> bit-identical per lane.
__device__ __forceinline__ uint64_t f32x2pk(float a, float b) {
    uint64_t r; asm("mov.b64 %0, {%1,%2};" : "=l"(r) : "f"(a), "f"(b)); return r;
}
__device__ __forceinline__ void f32x2upk(uint64_t v, float& a, float& b) {
    asm("mov.b64 {%0,%1}, %2;" : "=f"(a), "=f"(b) : "l"(v));
}
__device__ __forceinline__ uint64_t fma2(uint64_t a, uint64_t b, uint64_t c) {
    uint64_t d; asm("fma.rn.f32x2 %0,%1,%2,%3;" : "=l"(d) : "l"(a), "l"(b), "l"(c)); return d;
}
__device__ __forceinline__ uint64_t mul2(uint64_t a, uint64_t b) {
    uint64_t d; asm("mul.rn.f32x2 %0,%1,%2;" : "=l"(d) : "l"(a), "l"(b)); return d;
}
__device__ __forceinline__ uint64_t add2(uint64_t a, uint64_t b) {
    uint64_t d; asm("add.rn.f32x2 %0,%1,%2;" : "=l"(d) : "l"(a), "l"(b)); return d;
}

// Pairwise accurate exp: per-lane op sequence IDENTICAL to the scalar exp_rn
// used in R5-R12 (same constants, same RN roundings) -> bit-identical results.
__device__ __forceinline__ void exp_rn2(float x0, float x1, float& o0, float& o1) {
    x0 = fmaxf(x0, -87.0f); x1 = fmaxf(x1, -87.0f);
    uint64_t X = f32x2pk(x0, x1);
    uint64_t T = fma2(X, f32x2pk(1.44269504088896341f, 1.44269504088896341f),
                         f32x2pk(0.5f, 0.5f));
    float t0, t1; f32x2upk(T, t0, t1);
    float mf0 = floorf(t0), mf1 = floorf(t1);
    uint64_t MF = f32x2pk(mf0, mf1);
    uint64_t R = fma2(MF, f32x2pk(-0.693359375f, -0.693359375f), X);
    R = fma2(MF, f32x2pk(2.12194440e-4f, 2.12194440e-4f), R);
    uint64_t P = f32x2pk(1.9875691500e-4f, 1.9875691500e-4f);
    P = fma2(P, R, f32x2pk(1.3981999507e-3f, 1.3981999507e-3f));
    P = fma2(P, R, f32x2pk(8.3334519073e-3f, 8.3334519073e-3f));
    P = fma2(P, R, f32x2pk(4.1665795894e-2f, 4.1665795894e-2f));
    P = fma2(P, R, f32x2pk(1.6666665459e-1f, 1.6666665459e-1f));
    P = fma2(P, R, f32x2pk(5.0000001201e-1f, 5.0000001201e-1f));
    uint64_t Y = fma2(P, mul2(R, R), R);
    Y = add2(Y, f32x2pk(1.0f, 1.0f));
    int mi0 = (int)mf0, mi1 = (int)mf1;
    uint64_t SC = f32x2pk(__int_as_float((mi0 + 127) << 23),
                          __int_as_float((mi1 + 127) << 23));
    Y = mul2(Y, SC);
    f32x2upk(Y, o0, o1);
}

// ------------------------- mma.sync m16n8k16 bf16 -----------------------------
__device__ __forceinline__ void mma_bf16(float c[4], const uint32_t a[4], const uint32_t b[2]) {
    asm volatile(
        "mma.sync.aligned.m16n8k16.row.col.f32.bf16.bf16.f32 "
        "{%0,%1,%2,%3}, {%4,%5,%6,%7}, {%8,%9}, {%0,%1,%2,%3};\n"
        : "+f"(c[0]), "+f"(c[1]), "+f"(c[2]), "+f"(c[3])
        : "r"(a[0]), "r"(a[1]), "r"(a[2]), "r"(a[3]), "r"(b[0]), "r"(b[1]));
}

__device__ __forceinline__ void ldsm_x4(uint32_t r[4], uint32_t addr) {
    asm volatile("ldmatrix.sync.aligned.m8n8.x4.shared.b16 {%0,%1,%2,%3}, [%4];"
                 : "=r"(r[0]), "=r"(r[1]), "=r"(r[2]), "=r"(r[3]) : "r"(addr));
}

// ------------------------- prep kernels ---------------------------------------
__global__ void k_conv_x(const float* __restrict__ x) {
    size_t i = ((size_t)blockIdx.x * 256 + threadIdx.x) * 4;
    float4 v = *(const float4*)(x + i);
    __nv_bfloat162 a, b;
    a.x = __float2bfloat16(v.x); a.y = __float2bfloat16(v.y);
    b.x = __float2bfloat16(v.z); b.y = __float2bfloat16(v.w);
    *(__nv_bfloat162*)(g_xb + i)     = a;
    *(__nv_bfloat162*)(g_xb + i + 2) = b;
}

__global__ void k_prepW(const float* __restrict__ Wq, const float* __restrict__ Wk,
                        const float* __restrict__ Wv, const float* __restrict__ Wo,
                        const float* __restrict__ bq, const float* __restrict__ bk,
                        const float* __restrict__ bv, const float* __restrict__ bo) {
    const float* W = (blockIdx.z == 0) ? Wq : (blockIdx.z == 1) ? Wk : (blockIdx.z == 2) ? Wv : Wo;
    __shared__ float tile[32][33];
    int n0 = blockIdx.x * 32, k0 = blockIdx.y * 32;
    for (int jj = threadIdx.y; jj < 32; jj += 8)
        tile[jj][threadIdx.x] = W[(size_t)(k0 + jj) * CC + n0 + threadIdx.x];
    if (blockIdx.y == 0 && threadIdx.y == 0) {           // fold bias prep in
        const float* p = (blockIdx.z == 0) ? bq : (blockIdx.z == 1) ? bk
                       : (blockIdx.z == 2) ? bv : bo;
        g_bias[blockIdx.z][n0 + threadIdx.x] = __float2bfloat16(p[n0 + threadIdx.x]);
    }
    __syncthreads();
    for (int jj = threadIdx.y; jj < 32; jj += 8)
        g_WT[blockIdx.z][(size_t)(n0 + jj) * CC + k0 + threadIdx.x] =
            __float2bfloat16(tile[threadIdx.x][jj]);
}

__global__ void k_rope() {
    int t = blockIdx.x, j = threadIdx.x;                 // j in 0..31
    double e = (double)(2 * j) / 64.0;
    float p32 = (float)pow(10000.0, e);                  // f32 rounding of pow
    float inv = __fdiv_rn(1.0f, p32);                    // f32 reciprocal
    float ang = __fmul_rn((float)t, inv);                // f32 angle
    g_cos[t * (HD/2) + j] = (float)cos((double)ang);
    g_sin[t * (HD/2) + j] = (float)sin((double)ang);
}

// ------------------------- GEMM: x@W (+bias, rope) / y@Wo --------------------
// 128x128 tile, k-tile 64, cp.async 2-stage pipeline, ldmatrix fragment loads.
#define GSTAGE 36864              /* bytes per stage: (A 128*72 + B 128*72) * 2B */
#define GSMEM  (2*GSTAGE)

__global__ __launch_bounds__(256) void k_gemm(int mode_base, float* __restrict__ outF)
{
    extern __shared__ unsigned char gsm[];
    const int mode = mode_base + blockIdx.z;             // 0=q 1=k 2=v 3=out-proj
    const __nv_bfloat16* __restrict__ A  = (mode < 3) ? g_xb : g_y;
    const __nv_bfloat16* __restrict__ Bt = g_WT[mode];
    const __nv_bfloat16* __restrict__ bs = g_bias[mode];
    const int m0 = blockIdx.y * 128;
    const int n0 = blockIdx.x * 128;

    const int tid = threadIdx.x;
    const int wid = tid >> 5, lane = tid & 31;
    const int g = lane >> 2, t4 = lane & 3;
    const int wm = wid & 3, wn = wid >> 2;
    const int lb = lane >> 3, lr = lane & 7;             // ldmatrix block id / row

    float acc[16][4];
    #pragma unroll
    for (int i = 0; i < 16; i++) { acc[i][0] = acc[i][1] = acc[i][2] = acc[i][3] = 0.f; }

    {
        __nv_bfloat16* sA = (__nv_bfloat16*)gsm;
        __nv_bfloat16* sB = (__nv_bfloat16*)(gsm + GSTAGE / 2);
        #pragma unroll
        for (int rep = 0; rep < 4; rep++) {
            int i = tid + rep * 256;
            int row = i >> 3, cg = i & 7;
            uint32_t da = (uint32_t)__cvta_generic_to_shared(sA + row * 72 + cg * 8);
            uint32_t db = (uint32_t)__cvta_generic_to_shared(sB + row * 72 + cg * 8);
            asm volatile("cp.async.cg.shared.global [%0], [%1], 16;\n"
                         :: "r"(da), "l"(A  + (size_t)(m0 + row) * CC + cg * 8));
            asm volatile("cp.async.cg.shared.global [%0], [%1], 16;\n"
                         :: "r"(db), "l"(Bt + (size_t)(n0 + row) * CC + cg * 8));
        }
        asm volatile("cp.async.commit_group;\n");
    }

    for (int it = 0; it < 16; it++) {
        asm volatile("cp.async.wait_group 0;\n");
        __syncthreads();
        if (it + 1 < 16) {
            int k0 = (it + 1) * 64;
            unsigned char* stg = gsm + ((it + 1) & 1) * GSTAGE;
            __nv_bfloat16* sA = (__nv_bfloat16*)stg;
            __nv_bfloat16* sB = (__nv_bfloat16*)(stg + GSTAGE / 2);
            #pragma unroll
            for (int rep = 0; rep < 4; rep++) {
                int i = tid + rep * 256;
                int row = i >> 3, cg = i & 7;
                uint32_t da = (uint32_t)__cvta_generic_to_shared(sA + row * 72 + cg * 8);
                uint32_t db = (uint32_t)__cvta_generic_to_shared(sB + row * 72 + cg * 8);
                asm volatile("cp.async.cg.shared.global [%0], [%1], 16;\n"
                             :: "r"(da), "l"(A  + (size_t)(m0 + row) * CC + k0 + cg * 8));
                asm volatile("cp.async.cg.shared.global [%0], [%1], 16;\n"
                             :: "r"(db), "l"(Bt + (size_t)(n0 + row) * CC + k0 + cg * 8));
            }
            asm volatile("cp.async.commit_group;\n");
        }
        const __nv_bfloat16* sA = (const __nv_bfloat16*)(gsm + (it & 1) * GSTAGE);
        const __nv_bfloat16* sB = (const __nv_bfloat16*)(gsm + (it & 1) * GSTAGE + GSTAGE / 2);
        #pragma unroll
        for (int ks = 0; ks < 64; ks += 16) {
            uint32_t af[2][4];
            #pragma unroll
            for (int mt = 0; mt < 2; mt++) {
                int row = wm * 32 + mt * 16 + (lb & 1) * 8 + lr;
                int col = ks + (lb >> 1) * 8;
                ldsm_x4(af[mt], (uint32_t)__cvta_generic_to_shared(sA + row * 72 + col));
            }
            uint32_t bfr[8][2];
            #pragma unroll
            for (int p = 0; p < 4; p++) {
                int row = wn * 64 + (2 * p + (lb >> 1)) * 8 + lr;
                int col = ks + (lb & 1) * 8;
                uint32_t q[4];
                ldsm_x4(q, (uint32_t)__cvta_generic_to_shared(sB + row * 72 + col));
                bfr[2 * p][0] = q[0]; bfr[2 * p][1] = q[1];
                bfr[2 * p + 1][0] = q[2]; bfr[2 * p + 1][1] = q[3];
            }
            #pragma unroll
            for (int mt = 0; mt < 2; mt++)
                #pragma unroll
                for (int nt = 0; nt < 8; nt++)
                    mma_bf16(acc[mt * 8 + nt], af[mt], bfr[nt]);
        }
    }

    #pragma unroll
    for (int mt = 0; mt < 2; mt++) {
        #pragma unroll
        for (int nt = 0; nt < 8; nt++) {
            float* c = acc[mt * 8 + nt];
            int col = n0 + wn * 64 + nt * 8 + 2 * t4;
            int r0  = m0 + wm * 32 + mt * 16 + g;
            #pragma unroll
            for (int hf = 0; hf < 2; hf++) {
                int row = r0 + hf * 8;
                __nv_bfloat16 eb = __hadd(__float2bfloat16(c[hf * 2 + 0]), bs[col]);
                __nv_bfloat16 ob = __hadd(__float2bfloat16(c[hf * 2 + 1]), bs[col + 1]);
                if (mode == 3) {
                    outF[(size_t)row * CC + col]     = __bfloat162float(eb);
                    outF[(size_t)row * CC + col + 1] = __bfloat162float(ob);
                } else {
                    int b = row >> 11, t = row & (TT - 1);
                    int h = col >> 6,  d = col & 63;
                    size_t oidx = ((size_t)(b * HH + h) * TT + t) * HD + d;
                    __nv_bfloat162 pr;
                    if (mode <= 1) {                         // rope for q,k
                        int j = d >> 1;
                        float cth = g_cos[t * (HD/2) + j], sth = g_sin[t * (HD/2) + j];
                        float ef = __bfloat162float(eb), of = __bfloat162float(ob);
                        float re = __fsub_rn(__fmul_rn(ef, cth), __fmul_rn(of, sth));
                        float ro = __fadd_rn(__fmul_rn(ef, sth), __fmul_rn(of, cth));
                        pr.x = __float2bfloat16(re);
                        pr.y = __float2bfloat16(ro);
                    } else {
                        pr.x = eb; pr.y = ob;
                    }
                    __nv_bfloat16* outp = (mode == 0) ? g_q : (mode == 1) ? g_k : g_v;
                    *(__nv_bfloat162*)(outp + oidx) = pr;
                }
            }
        }
    }
}

// --------- fused attention: QK^T + max + l (phase A) then softmax@V (phase B) --
__global__ __launch_bounds__(256) void k_att()
{
    __shared__ __align__(16) unsigned char buf[36864];
    __shared__ float sMax[2][64];
    __shared__ float sMfin[64];
    __shared__ float sLfin[64];

    const int qt = gridDim.x - 1 - blockIdx.x;           // heavy tiles first
    const int bh = blockIdx.y;
    const int q0 = qt * 64;
    const __nv_bfloat16* __restrict__ Q = g_q + (size_t)bh * TT * HD;
    const __nv_bfloat16* __restrict__ K = g_k + (size_t)bh * TT * HD;
    const __nv_bfloat16* __restrict__ V = g_v + (size_t)bh * TT * HD;

    const int tid = threadIdx.x;
    const int wid = tid >> 5, lane = tid & 31;
    const int g = lane >> 2, t4 = lane & 3;
    const int wm = wid & 3, wn = wid >> 2;
    const int r0 = wm * 16 + g;
    const int lb = lane >> 3, lr = lane & 7;             // ldmatrix block id / row

    // ===================== phase A: S = bf16(QK^T)*0.125, max, l ==============
    {
        __nv_bfloat16* sQ = (__nv_bfloat16*)buf;                     // 9216 B
        #pragma unroll
        for (int rep = 0; rep < 2; rep++) {
            int i = tid + rep * 256;
            int row = i >> 3, cg = i & 7;
            *(uint4*)&sQ[row * 72 + cg * 8] = *(const uint4*)(Q + (size_t)(q0 + row) * HD + cg * 8);
        }
        // prestage K tile 0
        #pragma unroll
        for (int rep = 0; rep < 2; rep++) {
            int i = tid + rep * 256;
            int row = i >> 3, cg = i & 7;
            uint32_t dst = (uint32_t)__cvta_generic_to_shared(buf + 9216 + (row * 72 + cg * 8) * 2);
            asm volatile("cp.async.cg.shared.global [%0], [%1], 16;\n"
                         :: "r"(dst), "l"(K + (size_t)row * HD + cg * 8));
        }
        asm volatile("cp.async.commit_group;\n");

        const int qg0 = q0 + r0, qg1 = qg0 + 8;
        float rmax0 = -INFINITY, rmax1 = -INFINITY;

        for (int kt = 0; kt <= qt; kt++) {
            asm volatile("cp.async.wait_group 0;\n");
            __syncthreads();
            if (kt < qt) {
                unsigned char* dstb = buf + 9216 + ((kt + 1) & 1) * 9216;
                #pragma unroll
                for (int rep = 0; rep < 2; rep++) {
                    int i = tid + rep * 256;
                    int row = i >> 3, cg = i & 7;
                    uint32_t dst = (uint32_t)__cvta_generic_to_shared(dstb + (row * 72 + cg * 8) * 2);
                    asm volatile("cp.async.cg.shared.global [%0], [%1], 16;\n"
                                 :: "r"(dst), "l"(K + (size_t)((kt + 1) * 64 + row) * HD + cg * 8));
                }
                asm volatile("cp.async.commit_group;\n");
            }
            const __nv_bfloat16* sKb = (const __nv_bfloat16*)(buf + 9216 + (kt & 1) * 9216);
            float acc[4][4] = {};
            #pragma unroll
            for (int ks = 0; ks < 64; ks += 16) {
                uint32_t af[4];
                {
                    int row = wm * 16 + (lb & 1) * 8 + lr;
                    int col = ks + (lb >> 1) * 8;
                    ldsm_x4(af, (uint32_t)__cvta_generic_to_shared(sQ + row * 72 + col));
                }
                uint32_t kf[4][2];
                #pragma unroll
                for (int p = 0; p < 2; p++) {
                    int row = wn * 32 + (2 * p + (lb >> 1)) * 8 + lr;
                    int col = ks + (lb & 1) * 8;
                    uint32_t q4[4];
                    ldsm_x4(q4, (uint32_t)__cvta_generic_to_shared(sKb + row * 72 + col));
                    kf[2 * p][0] = q4[0]; kf[2 * p][1] = q4[1];
                    kf[2 * p + 1][0] = q4[2]; kf[2 * p + 1][1] = q4[3];
                }
                #pragma unroll
                for (int nt = 0; nt < 4; nt++)
                    mma_bf16(acc[nt], af, kf[nt]);
            }
            #pragma unroll
            for (int nt = 0; nt < 4; nt++) {
                int cl = wn * 32 + nt * 8 + 2 * t4;
                int kc = kt * 64 + cl;
                {
                    float s0 = __fmul_rn(__bfloat162float(__float2bfloat16(acc[nt][0])), 0.125f);
                    float s1 = __fmul_rn(__bfloat162float(__float2bfloat16(acc[nt][1])), 0.125f);
                    if (kc     <= qg0) rmax0 = fmaxf(rmax0, s0);
                    if (kc + 1 <= qg0) rmax0 = fmaxf(rmax0, s1);
                    __nv_bfloat162 pr; pr.x = __float2bfloat16(s0); pr.y = __float2bfloat16(s1);
                    *(__nv_bfloat162*)(g_S + (size_t)(bh * TT + qg0) * TT + kc) = pr;
                }
                {
                    float s0 = __fmul_rn(__bfloat162float(__float2bfloat16(acc[nt][2])), 0.125f);
                    float s1 = __fmul_rn(__bfloat162float(__float2bfloat16(acc[nt][3])), 0.125f);
                    if (kc     <= qg1) rmax1 = fmaxf(rmax1, s0);
                    if (kc + 1 <= qg1) rmax1 = fmaxf(rmax1, s1);
                    __nv_bfloat162 pr; pr.x = __float2bfloat16(s0); pr.y = __float2bfloat16(s1);
                    *(__nv_bfloat162*)(g_S + (size_t)(bh * TT + qg1) * TT + kc) = pr;
                }
            }
        }
        rmax0 = fmaxf(rmax0, __shfl_xor_sync(0xffffffffu, rmax0, 1));
        rmax0 = fmaxf(rmax0, __shfl_xor_sync(0xffffffffu, rmax0, 2));
        rmax1 = fmaxf(rmax1, __shfl_xor_sync(0xffffffffu, rmax1, 1));
        rmax1 = fmaxf(rmax1, __shfl_xor_sync(0xffffffffu, rmax1, 2));
        if (t4 == 0) {
            sMax[wn][wm * 16 + g]     = rmax0;
            sMax[wn][wm * 16 + g + 8] = rmax1;
        }
        __syncthreads();
        if (tid < 64) sMfin[tid] = fmaxf(sMax[0][tid], sMax[1][tid]);
        __syncthreads();   // S stripe writes + sMfin visible; all phase-A mma done

        // V tile 0 prestage NOW (sK buffers dead) — lands during the l-pass.
        #pragma unroll
        for (int rep = 0; rep < 2; rep++) {
            int i = tid + rep * 256;
            int row = i >> 3, cg = i & 7;
            uint32_t dst = (uint32_t)__cvta_generic_to_shared(buf + 18432 + (row * 72 + cg * 8) * 2);
            asm volatile("cp.async.cg.shared.global [%0], [%1], 16;\n"
                         :: "r"(dst), "l"(V + (size_t)row * HD + cg * 8));
        }
        asm volatile("cp.async.commit_group;\n");

        // l-pass over own stripe (L2-hot); adds in same order, exps bit-identical
        {
            const int prow = tid >> 2;
            const int pcb  = (tid & 3) * 16;
            const int qgp  = q0 + prow;
            const float mrow = sMfin[prow];
            const __nv_bfloat16* __restrict__ Srow = g_S + (size_t)(bh * TT + qgp) * TT;
            float lp = 0.f;
            uint4 c0 = *(const uint4*)(Srow + pcb);
            uint4 c1 = *(const uint4*)(Srow + pcb + 8);
            for (int kt = 0; kt <= qt; kt++) {
                uint4 n0v, n1v;
                if (kt < qt) {
                    n0v = *(const uint4*)(Srow + (kt + 1) * 64 + pcb);
                    n1v = *(const uint4*)(Srow + (kt + 1) * 64 + pcb + 8);
                }
                __nv_bfloat16 hv[16];
                *(uint4*)&hv[0] = c0;
                *(uint4*)&hv[8] = c1;
                #pragma unroll
                for (int j = 0; j < 16; j += 2) {
                    int col = kt * 64 + pcb + j;
                    float e0, e1;
                    exp_rn2(__fsub_rn(__bfloat162float(hv[j]),     mrow),
                            __fsub_rn(__bfloat162float(hv[j + 1]), mrow), e0, e1);
                    if (col     <= qgp) lp = __fadd_rn(lp, e0);
                    if (col + 1 <= qgp) lp = __fadd_rn(lp, e1);
                }
                c0 = n0v; c1 = n1v;
            }
            lp = __fadd_rn(lp, __shfl_xor_sync(0xffffffffu, lp, 1));
            lp = __fadd_rn(lp, __shfl_xor_sync(0xffffffffu, lp, 2));
            if ((tid & 3) == 0) sLfin[qgp - q0] = lp;
        }
    }
    __syncthreads();   // sLfin ready; phase A smem (sQ/sK) dead from here

    // ===================== phase B: p = bf16(softmax), y = P@V^T ===============
    // V staged untransposed [kseq][72] via cp.async; B-fragments via ldmatrix.trans.
    {
        const int prow = tid >> 2;
        const int pcb  = (tid & 3) * 16;
        const int qgp  = q0 + prow;
        const float mrow = sMfin[prow];
        const float lrow = sLfin[prow];
        const __nv_bfloat16* __restrict__ Srow = g_S + (size_t)(bh * TT + qgp) * TT;

        float acc[4][4] = {};
        const int l16 = lane & 15;

        // prolog: prefetch S chunk(kt=0) into regs (V tile 0 already in flight)
        uint4 s0 = *(const uint4*)(Srow + pcb);
        uint4 s1 = *(const uint4*)(Srow + pcb + 8);

        for (int kt = 0; kt <= qt; kt++) {
            const int bsel = kt & 1;
            __nv_bfloat16* sPb = (__nv_bfloat16*)(buf + bsel * 9216);
            const __nv_bfloat16* sVb = (const __nv_bfloat16*)(buf + 18432 + bsel * 9216);
            // probabilities from prefetched S regs (bf16, reference rounding)
            {
                __nv_bfloat16 hv[16];
                *(uint4*)&hv[0] = s0;
                *(uint4*)&hv[8] = s1;
                #pragma unroll
                for (int j = 0; j < 16; j += 2) {
                    int col = kt * 64 + pcb + j;
                    float e0, e1;
                    exp_rn2(__fsub_rn(__bfloat162float(hv[j]),     mrow),
                            __fsub_rn(__bfloat162float(hv[j + 1]), mrow), e0, e1);
                    __nv_bfloat162 pr;
                    pr.x = (col     <= qgp) ? __float2bfloat16(__fdiv_rn(e0, lrow))
                                            : __float2bfloat16(0.f);
                    pr.y = (col + 1 <= qgp) ? __float2bfloat16(__fdiv_rn(e1, lrow))
                                            : __float2bfloat16(0.f);
                    *(__nv_bfloat162*)&sPb[prow * 72 + pcb + j] = pr;
                }
            }
            asm volatile("cp.async.wait_group 0;\n");
            __syncthreads();            // sP[bsel] + V(kt) visible; prev mma done
            if (kt < qt) {
                unsigned char* dstb = buf + 18432 + ((kt + 1) & 1) * 9216;
                #pragma unroll
                for (int rep = 0; rep < 2; rep++) {
                    int i = tid + rep * 256;
                    int row = i >> 3, cg = i & 7;
                    uint32_t dst = (uint32_t)__cvta_generic_to_shared(dstb + (row * 72 + cg * 8) * 2);
                    asm volatile("cp.async.cg.shared.global [%0], [%1], 16;\n"
                                 :: "r"(dst), "l"(V + (size_t)((kt + 1) * 64 + row) * HD + cg * 8));
                }
                asm volatile("cp.async.commit_group;\n");
                s0 = *(const uint4*)(Srow + (kt + 1) * 64 + pcb);
                s1 = *(const uint4*)(Srow + (kt + 1) * 64 + pcb + 8);
            }
            #pragma unroll
            for (int ks = 0; ks < 64; ks += 16) {
                uint32_t af[4];
                {
                    int row = wm * 16 + (lb & 1) * 8 + lr;
                    int col = ks + (lb >> 1) * 8;
                    ldsm_x4(af, (uint32_t)__cvta_generic_to_shared(sPb + row * 72 + col));
                }
                #pragma unroll
                for (int nt = 0; nt < 4; nt++) {
                    int n0c = wn * 32 + nt * 8;
                    uint32_t vaddr = (uint32_t)__cvta_generic_to_shared(
                        sVb + (size_t)(ks + l16) * 72 + n0c);
                    uint32_t b2[2];
                    asm volatile(
                        "ldmatrix.sync.aligned.m8n8.x2.trans.shared.b16 {%0,%1}, [%2];"
                        : "=r"(b2[0]), "=r"(b2[1]) : "r"(vaddr));
                    mma_bf16(acc[nt], af, b2);
                }
            }
        }

        const int b = bh >> 4, h = bh & 15;
        #pragma unroll
        for (int nt = 0; nt < 4; nt++) {
            int dcol = wn * 32 + nt * 8 + 2 * t4;
            #pragma unroll
            for (int hf = 0; hf < 2; hf++) {
                int trow = q0 + r0 + hf * 8;
                __nv_bfloat162 pr;
                pr.x = __float2bfloat16(acc[nt][hf * 2 + 0]);
                pr.y = __float2bfloat16(acc[nt][hf * 2 + 1]);
                *(__nv_bfloat162*)(g_y + (size_t)(b * TT + trow) * CC + h * HD + dcol) = pr;
            }
        }
    }
}

// ------------------------- launch ---------------------------------------------
extern "C" void kernel_launch(void* const* d_in, const int* in_sizes, int n_in,
                              void* d_out, int out_size)
{
    (void)in_sizes; (void)n_in; (void)out_size;
    const float* x  = (const float*)d_in[0];
    const float* Wq = (const float*)d_in[1];
    const float* bq = (const float*)d_in[2];
    const float* Wk = (const float*)d_in[3];
    const float* bk = (const float*)d_in[4];
    const float* Wv = (const float*)d_in[5];
    const float* bv = (const float*)d_in[6];
    const float* Wo = (const float*)d_in[7];
    const float* bo = (const float*)d_in[8];
    float* out = (float*)d_out;

    cudaFuncSetAttribute(k_gemm, cudaFuncAttributeMaxDynamicSharedMemorySize, GSMEM);

    k_conv_x  <<<(size_t)MM * CC / 1024, 256>>>(x);
    k_prepW   <<<dim3(32, 32, 4), dim3(32, 8)>>>(Wq, Wk, Wv, Wo, bq, bk, bv, bo);
    k_rope    <<<TT, 32>>>();
    k_gemm    <<<dim3(8, 64, 3), 256, GSMEM>>>(0, nullptr);   // q,k,v projections (+rope)
    k_att     <<<dim3(32, 64), 256>>>();                      // fused attention
    k_gemm    <<<dim3(8, 64, 1), 256, GSMEM>>>(3, out);       // output projection
}